// round 13
// baseline (speedup 1.0000x reference)
#include <cuda_runtime.h>
#include <cuda_fp16.h>
#include <math.h>
#include <stdint.h>

#define Bb 8
#define Tt 2048
#define Cc 768
#define Hh 64
#define M_TOT (Bb*Tt)

// fp16 scratch (half2 packed in uint32)
__device__ uint32_t g_xh[M_TOT*Cc/2];    // x as fp16 [row][k]
__device__ uint32_t g_wth[192*Cc/2];     // fused transposed weights fp16 [n][k]
__device__ uint32_t g_qh[M_TOT*32];      // q fp16 [row][h]
__device__ uint32_t g_kh[M_TOT*32];
__device__ uint32_t g_vh[M_TOT*32];
// split-KV partials (up to 4 splits)
__device__ float g_po[4 * M_TOT * 64];
__device__ float g_pm[4 * M_TOT];
__device__ float g_pl[4 * M_TOT];

// ---------------------------------------------------------------------------
// helpers
// ---------------------------------------------------------------------------
__device__ __forceinline__ void mma_fp16(float* d, const uint32_t* a,
                                         uint32_t b0, uint32_t b1) {
    asm volatile(
        "mma.sync.aligned.m16n8k16.row.col.f32.f16.f16.f32 "
        "{%0,%1,%2,%3}, {%4,%5,%6,%7}, {%8,%9}, {%0,%1,%2,%3};"
        : "+f"(d[0]), "+f"(d[1]), "+f"(d[2]), "+f"(d[3])
        : "r"(a[0]), "r"(a[1]), "r"(a[2]), "r"(a[3]), "r"(b0), "r"(b1));
}

__device__ __forceinline__ void ldsm_x4(uint32_t& d0, uint32_t& d1,
                                        uint32_t& d2, uint32_t& d3,
                                        uint32_t saddr) {
    asm volatile("ldmatrix.sync.aligned.m8n8.x4.shared.b16 {%0,%1,%2,%3}, [%4];"
                 : "=r"(d0), "=r"(d1), "=r"(d2), "=r"(d3) : "r"(saddr));
}

__device__ __forceinline__ void ldsm_x4_t(uint32_t& d0, uint32_t& d1,
                                          uint32_t& d2, uint32_t& d3,
                                          uint32_t saddr) {
    asm volatile("ldmatrix.sync.aligned.m8n8.x4.trans.shared.b16 {%0,%1,%2,%3}, [%4];"
                 : "=r"(d0), "=r"(d1), "=r"(d2), "=r"(d3) : "r"(saddr));
}

__device__ __forceinline__ uint32_t smem_u32(const void* p) {
    uint32_t a;
    asm("{ .reg .u64 t; cvta.to.shared.u64 t, %1; cvt.u32.u64 %0, t; }"
        : "=r"(a) : "l"(p));
    return a;
}

__device__ __forceinline__ uint32_t h2pack(float x, float y) {
    __half2 h = __floats2half2_rn(x, y);
    return *(uint32_t*)&h;
}

// ---------------------------------------------------------------------------
// Kernel 0a: transpose+fuse weights -> fp16 g_wth[n][k] (coalesced)
// ---------------------------------------------------------------------------
__global__ void wtrans(const float* __restrict__ Wq,
                       const float* __restrict__ Wk,
                       const float* __restrict__ Wv)
{
    __shared__ float s[64][65];
    const int wsel = blockIdx.x / 12;
    const int k0   = (blockIdx.x % 12) * 64;
    const float* W = (wsel == 0) ? Wq : (wsel == 1 ? Wk : Wv);
    const int tid = threadIdx.x;

#pragma unroll
    for (int r = 0; r < 16; r++) {
        int idx = r * 256 + tid;
        int k = idx >> 6, h = idx & 63;
        s[k][h] = W[(size_t)(k0 + k) * Hh + h];
    }
    __syncthreads();

#pragma unroll
    for (int r = 0; r < 8; r++) {
        int idx = r * 256 + tid;
        int h = idx >> 5, kw = idx & 31;
        g_wth[(size_t)(wsel * 64 + h) * (Cc / 2) + (k0 >> 1) + kw] =
            h2pack(s[2 * kw][h], s[2 * kw + 1][h]);
    }
}

// ---------------------------------------------------------------------------
// Kernel 0b: x -> fp16 g_xh
// ---------------------------------------------------------------------------
__global__ void xcvt(const float* __restrict__ x)
{
    int t = blockIdx.x * 256 + threadIdx.x;
    const float4* xp = (const float4*)x;
    float4 a = xp[2 * t], b = xp[2 * t + 1];
    uint4 o;
    o.x = h2pack(a.x, a.y); o.y = h2pack(a.z, a.w);
    o.z = h2pack(b.x, b.y); o.w = h2pack(b.z, b.w);
    *(uint4*)&g_xh[4 * t] = o;
}

// ---------------------------------------------------------------------------
// Kernel 1: QKV projection, 64-row M tiles (grid 256, 2 CTAs/SM resident).
// CTA tile 64(M) x 192(N fused), BK=32, double-buffered.
// 8 warps as 2(M) x 4(N): warp tile 32x48 = 2 x 6 m16n8k16 fragments.
// ---------------------------------------------------------------------------
#define BKh 32
#define NCH (Cc / BKh)
#define W_A 0                  // [2][64*20] words
#define W_B 2560               // [2][192*20] words
#define QKV_SMEM (10240 * 4)   // 40960 B

__global__ __launch_bounds__(256) void qkv_h()
{
    extern __shared__ uint32_t smw[];
    const uint32_t sb = smem_u32(smw);

    const int tid  = threadIdx.x;
    const int lane = tid & 31, wid = tid >> 5;
    const int m0   = blockIdx.x * 64;
    const int g    = lane >> 2, tig = lane & 3;
    const int wm   = wid & 1,  wn  = wid >> 1;

    // copy mappings: A 1 uint4/thread, B 3 uint4/thread per chunk
    const int rowA = tid >> 2, cwA = (tid & 3) << 2;
    int rowB[3], cwB[3];
#pragma unroll
    for (int r = 0; r < 3; r++) { int idx = r*256+tid; rowB[r]=idx>>2; cwB[r]=(idx&3)<<2; }

    const int a_lrow = wm * 32 + (lane & 15);
    const int a_kh   = ((lane >> 4) & 1) << 2;
    const int b_lrow = wn * 48 + ((lane >> 4) & 1) * 8 + (lane & 7);
    const int b_kh   = ((lane >> 3) & 1) << 2;

    float acc[2][6][4];
#pragma unroll
    for (int i = 0; i < 2; i++)
#pragma unroll
        for (int j = 0; j < 6; j++)
#pragma unroll
            for (int r = 0; r < 4; r++) acc[i][j][r] = 0.f;

    // prologue: chunk 0 -> buffer 0
    *(uint4*)&smw[W_A + rowA * 20 + cwA] =
        *(const uint4*)&g_xh[(size_t)(m0 + rowA) * (Cc/2) + cwA];
#pragma unroll
    for (int r = 0; r < 3; r++)
        *(uint4*)&smw[W_B + rowB[r] * 20 + cwB[r]] =
            *(const uint4*)&g_wth[(size_t)rowB[r] * (Cc/2) + cwB[r]];
    __syncthreads();

    for (int t = 0; t < NCH; t++) {
        const int buf = t & 1;
        uint4 stA, stB[3];
        if (t + 1 < NCH) {
            const int k0w = (t + 1) * (BKh / 2);
            stA = *(const uint4*)&g_xh[(size_t)(m0 + rowA) * (Cc/2) + k0w + cwA];
#pragma unroll
            for (int r = 0; r < 3; r++)
                stB[r] = *(const uint4*)&g_wth[(size_t)rowB[r] * (Cc/2) + k0w + cwB[r]];
        }

        const uint32_t Abase = sb + (W_A + buf * 1280) * 4;
        const uint32_t Bbase = sb + (W_B + buf * 3840) * 4;

#pragma unroll
        for (int kk2 = 0; kk2 < 16; kk2 += 8) {
            uint32_t a[2][4];
#pragma unroll
            for (int i = 0; i < 2; i++)
                ldsm_x4(a[i][0], a[i][1], a[i][2], a[i][3],
                        Abase + (uint32_t)(((a_lrow + i * 16) * 20 + kk2 + a_kh) * 4));
            uint32_t bf[6][2];
#pragma unroll
            for (int p = 0; p < 3; p++) {
                uint32_t d0, d1, d2, d3;
                ldsm_x4(d0, d1, d2, d3,
                        Bbase + (uint32_t)(((b_lrow + p * 16) * 20 + kk2 + b_kh) * 4));
                bf[2*p][0] = d0; bf[2*p][1] = d1;
                bf[2*p+1][0] = d2; bf[2*p+1][1] = d3;
            }
#pragma unroll
            for (int j = 0; j < 6; j++) {
                mma_fp16(acc[0][j], a[0], bf[j][0], bf[j][1]);
                mma_fp16(acc[1][j], a[1], bf[j][0], bf[j][1]);
            }
        }

        if (t + 1 < NCH) {
            uint32_t* Ad = smw + W_A + (buf ^ 1) * 1280;
            uint32_t* Bd = smw + W_B + (buf ^ 1) * 3840;
            *(uint4*)&Ad[rowA * 20 + cwA] = stA;
#pragma unroll
            for (int r = 0; r < 3; r++)
                *(uint4*)&Bd[rowB[r] * 20 + cwB[r]] = stB[r];
        }
        __syncthreads();
    }

    // epilogue: write fp16 q/k/v
#pragma unroll
    for (int i = 0; i < 2; i++) {
        int r0 = m0 + wm * 32 + i * 16 + g;
#pragma unroll
        for (int j = 0; j < 6; j++) {
            int c = wn * 48 + j * 8 + tig * 2;
            uint32_t* op = (c < 64) ? g_qh : (c < 128 ? g_kh : g_vh);
            int oc = (c & 63) >> 1;
            op[(size_t)r0 * 32 + oc]       = h2pack(acc[i][j][0], acc[i][j][1]);
            op[(size_t)(r0 + 8) * 32 + oc] = h2pack(acc[i][j][2], acc[i][j][3]);
        }
    }
}

// ---------------------------------------------------------------------------
// Kernel 2: causal flash attention, adaptive split-KV, ldmatrix S-path.
// ---------------------------------------------------------------------------
#define OQ  0
#define OKV 4608
#define ATTN_SMEM (13824 * 4)

__global__ __launch_bounds__(256, 2) void attn_mma(
    const float* __restrict__ amask)
{
    extern __shared__ uint32_t smw[];
    uint32_t* Qs = smw + OQ;
    const uint32_t sb = smem_u32(smw);

    const int b   = blockIdx.y;
    const int x   = blockIdx.x;
    int iq, part, ns;
    if (x < 16)      { iq = 15 - (x >> 2);        part = x & 3;        ns = 4; }
    else if (x < 28) { iq = 11 - (x - 16) / 3;    part = (x - 16) % 3; ns = 3; }
    else if (x < 36) { iq = 7  - ((x - 28) >> 1); part = (x - 28) & 1; ns = 2; }
    else             { iq = 3  - (x - 36);        part = 0;            ns = 1; }

    const int q0  = iq * 128;
    const int ntiles = 2 * iq + 2;
    const int base = ntiles / ns, rem = ntiles % ns;
    const int tstart = part * base + min(part, rem);
    const int tend   = tstart + base + (part < rem ? 1 : 0);

    const int tid = threadIdx.x;
    const int lane = tid & 31, w = tid >> 5;
    const int g = lane >> 2, t = lane & 3;

    // ldmatrix lane mappings (same as qkv, stride 36)
    const int a_lrow = w * 16 + (lane & 15);
    const int a_kh   = ((lane >> 4) & 1) << 2;
    const int b_lrow = ((lane >> 4) & 1) * 8 + (lane & 7);
    const int b_kh   = ((lane >> 3) & 1) << 2;

    // stage Q
    const uint32_t* qp = g_qh + ((size_t)b * Tt + q0) * 32;
#pragma unroll
    for (int r = 0; r < 4; r++) {
        int idx = r * 256 + tid;
        int row = idx >> 3, cw = (idx & 7) << 2;
        *(uint4*)&Qs[row * 36 + cw] = *(const uint4*)&qp[row * 32 + cw];
    }

    float m0 = -INFINITY, m1 = -INFINITY, l0 = 0.f, l1 = 0.f;
    float o[8][4];
#pragma unroll
    for (int f = 0; f < 8; f++)
#pragma unroll
        for (int r = 0; r < 4; r++) o[f][r] = 0.f;

    const float am0 = amask[(size_t)b * Tt + q0 + w * 16 + g];
    const float am1 = amask[(size_t)b * Tt + q0 + w * 16 + g + 8];
    const int qg0 = q0 + w * 16 + g;
    const int qg1 = qg0 + 8;

    int srow[2], scw[2];
#pragma unroll
    for (int r = 0; r < 2; r++) { int idx = r*256+tid; srow[r]=idx>>3; scw[r]=(idx&7)<<2; }

    // prologue: stage tile tstart into buffer 0
    {
        const uint32_t* kp = g_kh + ((size_t)b * Tt + tstart * 64) * 32;
        const uint32_t* vp = g_vh + ((size_t)b * Tt + tstart * 64) * 32;
        uint32_t* Kd = smw + OKV;
        uint32_t* Vd = smw + OKV + 2304;
#pragma unroll
        for (int r = 0; r < 2; r++) {
            *(uint4*)&Kd[srow[r] * 36 + scw[r]] = *(const uint4*)&kp[srow[r] * 32 + scw[r]];
            *(uint4*)&Vd[srow[r] * 36 + scw[r]] = *(const uint4*)&vp[srow[r] * 32 + scw[r]];
        }
    }
    __syncthreads();

    for (int tt = tstart; tt < tend; tt++) {
        const int cur = (tt - tstart) & 1;
        const int j0 = tt * 64;
        const bool more = (tt + 1 < tend);
        const bool interior = (j0 + 63 <= q0);   // no causal masking needed

        uint4 stK[2], stV[2];
        if (more) {
            const uint32_t* kp = g_kh + ((size_t)b * Tt + (tt + 1) * 64) * 32;
            const uint32_t* vp = g_vh + ((size_t)b * Tt + (tt + 1) * 64) * 32;
#pragma unroll
            for (int r = 0; r < 2; r++) {
                stK[r] = *(const uint4*)&kp[srow[r] * 32 + scw[r]];
                stV[r] = *(const uint4*)&vp[srow[r] * 32 + scw[r]];
            }
        }

        const uint32_t sbq = sb;
        const uint32_t sbk = sb + (uint32_t)((OKV + cur * 4608) * 4);
        const uint32_t sbv = sb + (uint32_t)((OKV + cur * 4608 + 2304) * 4);

        // S = Q K^T (all fragment loads via ldmatrix)
        float c[8][4];
#pragma unroll
        for (int f = 0; f < 8; f++)
#pragma unroll
            for (int r = 0; r < 4; r++) c[f][r] = 0.f;
#pragma unroll
        for (int ks = 0; ks < 4; ks++) {
            uint32_t a[4];
            ldsm_x4(a[0], a[1], a[2], a[3],
                    sbq + (uint32_t)((a_lrow * 36 + ks * 8 + a_kh) * 4));
            uint32_t bf[8][2];
#pragma unroll
            for (int p = 0; p < 4; p++) {
                uint32_t d0, d1, d2, d3;
                ldsm_x4(d0, d1, d2, d3,
                        sbk + (uint32_t)(((b_lrow + p * 16) * 36 + ks * 8 + b_kh) * 4));
                bf[2*p][0] = d0; bf[2*p][1] = d1;
                bf[2*p+1][0] = d2; bf[2*p+1][1] = d3;
            }
#pragma unroll
            for (int f = 0; f < 8; f++)
                mma_fp16(c[f], a, bf[f][0], bf[f][1]);
        }

        // masks
        float mx0 = -INFINITY, mx1 = -INFINITY;
        if (interior) {
#pragma unroll
            for (int f = 0; f < 8; f++) {
                float v0 = c[f][0] * 0.125f * am0;
                float v1 = c[f][1] * 0.125f * am0;
                float v2 = c[f][2] * 0.125f * am1;
                float v3 = c[f][3] * 0.125f * am1;
                if (v0 == 0.f) v0 = -INFINITY;
                if (v1 == 0.f) v1 = -INFINITY;
                if (v2 == 0.f) v2 = -INFINITY;
                if (v3 == 0.f) v3 = -INFINITY;
                c[f][0] = v0; c[f][1] = v1; c[f][2] = v2; c[f][3] = v3;
                mx0 = fmaxf(mx0, fmaxf(v0, v1));
                mx1 = fmaxf(mx1, fmaxf(v2, v3));
            }
        } else {
#pragma unroll
            for (int f = 0; f < 8; f++) {
                int col = j0 + f * 8 + t * 2;
                float v0 = c[f][0] * 0.125f * am0;
                float v1 = c[f][1] * 0.125f * am0;
                float v2 = c[f][2] * 0.125f * am1;
                float v3 = c[f][3] * 0.125f * am1;
                if (v0 == 0.f || col     > qg0) v0 = -INFINITY;
                if (v1 == 0.f || col + 1 > qg0) v1 = -INFINITY;
                if (v2 == 0.f || col     > qg1) v2 = -INFINITY;
                if (v3 == 0.f || col + 1 > qg1) v3 = -INFINITY;
                c[f][0] = v0; c[f][1] = v1; c[f][2] = v2; c[f][3] = v3;
                mx0 = fmaxf(mx0, fmaxf(v0, v1));
                mx1 = fmaxf(mx1, fmaxf(v2, v3));
            }
        }
        mx0 = fmaxf(mx0, __shfl_xor_sync(0xffffffffu, mx0, 1));
        mx0 = fmaxf(mx0, __shfl_xor_sync(0xffffffffu, mx0, 2));
        mx1 = fmaxf(mx1, __shfl_xor_sync(0xffffffffu, mx1, 1));
        mx1 = fmaxf(mx1, __shfl_xor_sync(0xffffffffu, mx1, 2));

        float mn0 = fmaxf(m0, mx0), mn1 = fmaxf(m1, mx1);
        float alpha0, alpha1, ls0 = 0.f, ls1 = 0.f;
        uint32_t p01[8], p23[8];
        if (mn0 == -INFINITY) {
            alpha0 = 1.f;
#pragma unroll
            for (int f = 0; f < 8; f++) { c[f][0] = 0.f; c[f][1] = 0.f; }
        } else {
            alpha0 = __expf(m0 - mn0);
#pragma unroll
            for (int f = 0; f < 8; f++) {
                c[f][0] = __expf(c[f][0] - mn0);
                c[f][1] = __expf(c[f][1] - mn0);
                ls0 += c[f][0] + c[f][1];
            }
        }
        if (mn1 == -INFINITY) {
            alpha1 = 1.f;
#pragma unroll
            for (int f = 0; f < 8; f++) { c[f][2] = 0.f; c[f][3] = 0.f; }
        } else {
            alpha1 = __expf(m1 - mn1);
#pragma unroll
            for (int f = 0; f < 8; f++) {
                c[f][2] = __expf(c[f][2] - mn1);
                c[f][3] = __expf(c[f][3] - mn1);
                ls1 += c[f][2] + c[f][3];
            }
        }
        m0 = mn0; m1 = mn1;
        ls0 += __shfl_xor_sync(0xffffffffu, ls0, 1);
        ls0 += __shfl_xor_sync(0xffffffffu, ls0, 2);
        ls1 += __shfl_xor_sync(0xffffffffu, ls1, 1);
        ls1 += __shfl_xor_sync(0xffffffffu, ls1, 2);
        l0 = l0 * alpha0 + ls0;
        l1 = l1 * alpha1 + ls1;

#pragma unroll
        for (int f = 0; f < 8; f++) {
            p01[f] = h2pack(c[f][0], c[f][1]);
            p23[f] = h2pack(c[f][2], c[f][3]);
            o[f][0] *= alpha0; o[f][1] *= alpha0;
            o[f][2] *= alpha1; o[f][3] *= alpha1;
        }

        // O += P V
        const int vrow = (lane & 15);
        const int vcb  = ((lane >> 4) & 1) << 2;
#pragma unroll
        for (int ss = 0; ss < 4; ss++) {
            uint32_t a[4];
            a[0] = p01[2 * ss];     a[1] = p23[2 * ss];
            a[2] = p01[2 * ss + 1]; a[3] = p23[2 * ss + 1];
#pragma unroll
            for (int p = 0; p < 4; p++) {
                uint32_t d0, d1, d2, d3;
                ldsm_x4_t(d0, d1, d2, d3,
                          sbv + (uint32_t)((((ss * 16 + vrow) * 36) + p * 8 + vcb) * 4));
                mma_fp16(o[2 * p],     a, d0, d1);
                mma_fp16(o[2 * p + 1], a, d2, d3);
            }
        }

        if (more) {
            uint32_t* Kd = smw + OKV + (cur ^ 1) * 4608;
            uint32_t* Vd = Kd + 2304;
#pragma unroll
            for (int r = 0; r < 2; r++) {
                *(uint4*)&Kd[srow[r] * 36 + scw[r]] = stK[r];
                *(uint4*)&Vd[srow[r] * 36 + scw[r]] = stV[r];
            }
        }
        __syncthreads();
    }

    // epilogue: write unnormalized partials into slot `part`
    float* po0 = g_po + ((size_t)part * M_TOT + (size_t)b * Tt + qg0) * 64;
    float* po1 = g_po + ((size_t)part * M_TOT + (size_t)b * Tt + qg1) * 64;
#pragma unroll
    for (int f = 0; f < 8; f++) {
        int col = f * 8 + t * 2;
        *(float2*)(po0 + col) = make_float2(o[f][0], o[f][1]);
        *(float2*)(po1 + col) = make_float2(o[f][2], o[f][3]);
    }
    if (t == 0) {
        size_t r0 = (size_t)part * M_TOT + (size_t)b * Tt + qg0;
        size_t r1 = (size_t)part * M_TOT + (size_t)b * Tt + qg1;
        g_pm[r0] = m0; g_pl[r0] = l0;
        g_pm[r1] = m1; g_pl[r1] = l1;
    }
}

// ---------------------------------------------------------------------------
// Kernel 3: combine up to 4 splits
// ---------------------------------------------------------------------------
__global__ void combine(float* __restrict__ out)
{
    int idx = blockIdx.x * 256 + threadIdx.x;
    int row = idx >> 4;
    int c4  = (idx & 15) << 2;
    int iq  = (row & (Tt - 1)) >> 7;
    int ns  = (iq >= 12) ? 4 : (iq >= 8) ? 3 : (iq >= 4) ? 2 : 1;

    float mv[4], lv[4];
    float M = -INFINITY;
    for (int s = 0; s < ns; s++) {
        mv[s] = g_pm[(size_t)s * M_TOT + row];
        lv[s] = g_pl[(size_t)s * M_TOT + row];
        M = fmaxf(M, mv[s]);
    }
    float l = 0.f;
    float wv[4];
    for (int s = 0; s < ns; s++) {
        wv[s] = (mv[s] == -INFINITY) ? 0.f : __expf(mv[s] - M);
        l += lv[s] * wv[s];
    }
    float inv = (l > 0.f) ? (1.f / l) : 0.f;

    float4 acc = make_float4(0.f, 0.f, 0.f, 0.f);
    for (int s = 0; s < ns; s++) {
        float4 a = *(const float4*)&g_po[((size_t)s * M_TOT + row) * 64 + c4];
        acc.x += a.x * wv[s]; acc.y += a.y * wv[s];
        acc.z += a.z * wv[s]; acc.w += a.w * wv[s];
    }
    acc.x *= inv; acc.y *= inv; acc.z *= inv; acc.w *= inv;
    *(float4*)&out[(size_t)row * 64 + c4] = acc;
}

// ---------------------------------------------------------------------------
extern "C" void kernel_launch(void* const* d_in, const int* in_sizes, int n_in,
                              void* d_out, int out_size)
{
    const float* x  = (const float*)d_in[0];
    const float* am = (const float*)d_in[1];
    const float* Wq = (const float*)d_in[2];
    const float* Wk = (const float*)d_in[3];
    const float* Wv = (const float*)d_in[4];
    float*       out = (float*)d_out;

    wtrans<<<36, 256>>>(Wq, Wk, Wv);
    xcvt<<<(M_TOT * Cc / 8) / 256, 256>>>(x);

    cudaFuncSetAttribute(qkv_h,
                         cudaFuncAttributeMaxDynamicSharedMemorySize, QKV_SMEM);
    qkv_h<<<M_TOT / 64, 256, QKV_SMEM>>>();

    cudaFuncSetAttribute(attn_mma,
                         cudaFuncAttributeMaxDynamicSharedMemorySize, ATTN_SMEM);
    dim3 g2(40, Bb);
    attn_mma<<<g2, 256, ATTN_SMEM>>>(am);

    combine<<<(M_TOT * 16) / 256, 256>>>(out);
}

// round 14
// speedup vs baseline: 1.0826x; 1.0826x over previous
#include <cuda_runtime.h>
#include <cuda_fp16.h>
#include <math.h>
#include <stdint.h>

#define Bb 8
#define Tt 2048
#define Cc 768
#define Hh 64
#define M_TOT (Bb*Tt)

// fp16 scratch (half2 packed in uint32)
__device__ uint32_t g_xh[M_TOT*Cc/2];    // x as fp16 [row][k]
__device__ uint32_t g_wth[192*Cc/2];     // fused transposed weights fp16 [n][k]
__device__ uint32_t g_qh[M_TOT*32];      // q fp16 [row][h]
__device__ uint32_t g_kh[M_TOT*32];
__device__ uint32_t g_vh[M_TOT*32];
// split-KV partials (up to 4 splits)
__device__ float g_po[4 * M_TOT * 64];
__device__ float g_pm[4 * M_TOT];
__device__ float g_pl[4 * M_TOT];

// ---------------------------------------------------------------------------
// helpers
// ---------------------------------------------------------------------------
__device__ __forceinline__ void mma_fp16(float* d, const uint32_t* a,
                                         uint32_t b0, uint32_t b1) {
    asm volatile(
        "mma.sync.aligned.m16n8k16.row.col.f32.f16.f16.f32 "
        "{%0,%1,%2,%3}, {%4,%5,%6,%7}, {%8,%9}, {%0,%1,%2,%3};"
        : "+f"(d[0]), "+f"(d[1]), "+f"(d[2]), "+f"(d[3])
        : "r"(a[0]), "r"(a[1]), "r"(a[2]), "r"(a[3]), "r"(b0), "r"(b1));
}

__device__ __forceinline__ void ldsm_x4(uint32_t& d0, uint32_t& d1,
                                        uint32_t& d2, uint32_t& d3,
                                        uint32_t saddr) {
    asm volatile("ldmatrix.sync.aligned.m8n8.x4.shared.b16 {%0,%1,%2,%3}, [%4];"
                 : "=r"(d0), "=r"(d1), "=r"(d2), "=r"(d3) : "r"(saddr));
}

__device__ __forceinline__ void ldsm_x4_t(uint32_t& d0, uint32_t& d1,
                                          uint32_t& d2, uint32_t& d3,
                                          uint32_t saddr) {
    asm volatile("ldmatrix.sync.aligned.m8n8.x4.trans.shared.b16 {%0,%1,%2,%3}, [%4];"
                 : "=r"(d0), "=r"(d1), "=r"(d2), "=r"(d3) : "r"(saddr));
}

__device__ __forceinline__ uint32_t smem_u32(const void* p) {
    uint32_t a;
    asm("{ .reg .u64 t; cvta.to.shared.u64 t, %1; cvt.u32.u64 %0, t; }"
        : "=r"(a) : "l"(p));
    return a;
}

__device__ __forceinline__ uint32_t h2pack(float x, float y) {
    __half2 h = __floats2half2_rn(x, y);
    return *(uint32_t*)&h;
}

// ---------------------------------------------------------------------------
// Kernel 0a: transpose+fuse weights -> fp16 g_wth[n][k] (coalesced)
// ---------------------------------------------------------------------------
__global__ void wtrans(const float* __restrict__ Wq,
                       const float* __restrict__ Wk,
                       const float* __restrict__ Wv)
{
    __shared__ float s[64][65];
    const int wsel = blockIdx.x / 12;
    const int k0   = (blockIdx.x % 12) * 64;
    const float* W = (wsel == 0) ? Wq : (wsel == 1 ? Wk : Wv);
    const int tid = threadIdx.x;

#pragma unroll
    for (int r = 0; r < 16; r++) {
        int idx = r * 256 + tid;
        int k = idx >> 6, h = idx & 63;
        s[k][h] = W[(size_t)(k0 + k) * Hh + h];
    }
    __syncthreads();

#pragma unroll
    for (int r = 0; r < 8; r++) {
        int idx = r * 256 + tid;
        int h = idx >> 5, kw = idx & 31;
        g_wth[(size_t)(wsel * 64 + h) * (Cc / 2) + (k0 >> 1) + kw] =
            h2pack(s[2 * kw][h], s[2 * kw + 1][h]);
    }
}

// ---------------------------------------------------------------------------
// Kernel 0b: x -> fp16 g_xh
// ---------------------------------------------------------------------------
__global__ void xcvt(const float* __restrict__ x)
{
    int t = blockIdx.x * 256 + threadIdx.x;
    const float4* xp = (const float4*)x;
    float4 a = xp[2 * t], b = xp[2 * t + 1];
    uint4 o;
    o.x = h2pack(a.x, a.y); o.y = h2pack(a.z, a.w);
    o.z = h2pack(b.x, b.y); o.w = h2pack(b.z, b.w);
    *(uint4*)&g_xh[4 * t] = o;
}

// ---------------------------------------------------------------------------
// Kernel 1: QKV projection (R12 version: 128-row M tiles, grid 128).
// CTA tile 128(M) x 192(N fused), BK=32, double-buffered.
// 8 warps as 4(M)x2(N): warp tile 32x96 = 2 x 12 m16n8k16 fragments.
// ---------------------------------------------------------------------------
#define BKh 32
#define NCH (Cc / BKh)
#define W_A 0                  // [2][128*20] words
#define W_B 5120               // [2][192*20] words
#define QKV_SMEM (12800 * 4)   // 51200 B

__global__ __launch_bounds__(256) void qkv_h()
{
    extern __shared__ uint32_t smw[];
    const uint32_t sb = smem_u32(smw);

    const int tid  = threadIdx.x;
    const int lane = tid & 31, wid = tid >> 5;
    const int m0   = blockIdx.x * 128;
    const int g    = lane >> 2, tig = lane & 3;
    const int wm   = wid & 3,  wn  = wid >> 2;

    int rowA[2], cwA[2], rowB[3], cwB[3];
#pragma unroll
    for (int r = 0; r < 2; r++) { int idx = r*256+tid; rowA[r]=idx>>2; cwA[r]=(idx&3)<<2; }
#pragma unroll
    for (int r = 0; r < 3; r++) { int idx = r*256+tid; rowB[r]=idx>>2; cwB[r]=(idx&3)<<2; }

    const int a_lrow = wm * 32 + (lane & 15);
    const int a_kh   = ((lane >> 4) & 1) << 2;
    const int b_lrow = wn * 96 + ((lane >> 4) & 1) * 8 + (lane & 7);
    const int b_kh   = ((lane >> 3) & 1) << 2;

    float acc[2][12][4];
#pragma unroll
    for (int i = 0; i < 2; i++)
#pragma unroll
        for (int j = 0; j < 12; j++)
#pragma unroll
            for (int r = 0; r < 4; r++) acc[i][j][r] = 0.f;

#pragma unroll
    for (int r = 0; r < 2; r++)
        *(uint4*)&smw[W_A + rowA[r] * 20 + cwA[r]] =
            *(const uint4*)&g_xh[(size_t)(m0 + rowA[r]) * (Cc/2) + cwA[r]];
#pragma unroll
    for (int r = 0; r < 3; r++)
        *(uint4*)&smw[W_B + rowB[r] * 20 + cwB[r]] =
            *(const uint4*)&g_wth[(size_t)rowB[r] * (Cc/2) + cwB[r]];
    __syncthreads();

    for (int t = 0; t < NCH; t++) {
        const int buf = t & 1;
        uint4 stA[2], stB[3];
        if (t + 1 < NCH) {
            const int k0w = (t + 1) * (BKh / 2);
#pragma unroll
            for (int r = 0; r < 2; r++)
                stA[r] = *(const uint4*)&g_xh[(size_t)(m0 + rowA[r]) * (Cc/2) + k0w + cwA[r]];
#pragma unroll
            for (int r = 0; r < 3; r++)
                stB[r] = *(const uint4*)&g_wth[(size_t)rowB[r] * (Cc/2) + k0w + cwB[r]];
        }

        const uint32_t Abase = sb + (W_A + buf * 2560) * 4;
        const uint32_t Bbase = sb + (W_B + buf * 3840) * 4;

#pragma unroll
        for (int kk2 = 0; kk2 < 16; kk2 += 8) {
            uint32_t a[2][4];
#pragma unroll
            for (int i = 0; i < 2; i++)
                ldsm_x4(a[i][0], a[i][1], a[i][2], a[i][3],
                        Abase + (uint32_t)(((a_lrow + i * 16) * 20 + kk2 + a_kh) * 4));
            uint32_t bf[12][2];
#pragma unroll
            for (int p = 0; p < 6; p++) {
                uint32_t d0, d1, d2, d3;
                ldsm_x4(d0, d1, d2, d3,
                        Bbase + (uint32_t)(((b_lrow + p * 16) * 20 + kk2 + b_kh) * 4));
                bf[2*p][0] = d0; bf[2*p][1] = d1;
                bf[2*p+1][0] = d2; bf[2*p+1][1] = d3;
            }
#pragma unroll
            for (int j = 0; j < 12; j++) {
                mma_fp16(acc[0][j], a[0], bf[j][0], bf[j][1]);
                mma_fp16(acc[1][j], a[1], bf[j][0], bf[j][1]);
            }
        }

        if (t + 1 < NCH) {
            uint32_t* Ad = smw + W_A + (buf ^ 1) * 2560;
            uint32_t* Bd = smw + W_B + (buf ^ 1) * 3840;
#pragma unroll
            for (int r = 0; r < 2; r++)
                *(uint4*)&Ad[rowA[r] * 20 + cwA[r]] = stA[r];
#pragma unroll
            for (int r = 0; r < 3; r++)
                *(uint4*)&Bd[rowB[r] * 20 + cwB[r]] = stB[r];
        }
        __syncthreads();
    }

#pragma unroll
    for (int i = 0; i < 2; i++) {
        int r0 = m0 + wm * 32 + i * 16 + g;
#pragma unroll
        for (int j = 0; j < 12; j++) {
            int c = wn * 96 + j * 8 + tig * 2;
            uint32_t* op = (c < 64) ? g_qh : (c < 128 ? g_kh : g_vh);
            int oc = (c & 63) >> 1;
            op[(size_t)r0 * 32 + oc]       = h2pack(acc[i][j][0], acc[i][j][1]);
            op[(size_t)(r0 + 8) * 32 + oc] = h2pack(acc[i][j][2], acc[i][j][3]);
        }
    }
}

// ---------------------------------------------------------------------------
// Kernel 2: causal flash attention, adaptive split-KV, ldmatrix S-path
// (unchanged from R13 — measured 30.8us).
// ---------------------------------------------------------------------------
#define OQ  0
#define OKV 4608
#define ATTN_SMEM (13824 * 4)

__global__ __launch_bounds__(256, 2) void attn_mma(
    const float* __restrict__ amask)
{
    extern __shared__ uint32_t smw[];
    uint32_t* Qs = smw + OQ;
    const uint32_t sb = smem_u32(smw);

    const int b   = blockIdx.y;
    const int x   = blockIdx.x;
    int iq, part, ns;
    if (x < 16)      { iq = 15 - (x >> 2);        part = x & 3;        ns = 4; }
    else if (x < 28) { iq = 11 - (x - 16) / 3;    part = (x - 16) % 3; ns = 3; }
    else if (x < 36) { iq = 7  - ((x - 28) >> 1); part = (x - 28) & 1; ns = 2; }
    else             { iq = 3  - (x - 36);        part = 0;            ns = 1; }

    const int q0  = iq * 128;
    const int ntiles = 2 * iq + 2;
    const int base = ntiles / ns, rem = ntiles % ns;
    const int tstart = part * base + min(part, rem);
    const int tend   = tstart + base + (part < rem ? 1 : 0);

    const int tid = threadIdx.x;
    const int lane = tid & 31, w = tid >> 5;
    const int g = lane >> 2, t = lane & 3;

    const int a_lrow = w * 16 + (lane & 15);
    const int a_kh   = ((lane >> 4) & 1) << 2;
    const int b_lrow = ((lane >> 4) & 1) * 8 + (lane & 7);
    const int b_kh   = ((lane >> 3) & 1) << 2;

    // stage Q
    const uint32_t* qp = g_qh + ((size_t)b * Tt + q0) * 32;
#pragma unroll
    for (int r = 0; r < 4; r++) {
        int idx = r * 256 + tid;
        int row = idx >> 3, cw = (idx & 7) << 2;
        *(uint4*)&Qs[row * 36 + cw] = *(const uint4*)&qp[row * 32 + cw];
    }

    float m0 = -INFINITY, m1 = -INFINITY, l0 = 0.f, l1 = 0.f;
    float o[8][4];
#pragma unroll
    for (int f = 0; f < 8; f++)
#pragma unroll
        for (int r = 0; r < 4; r++) o[f][r] = 0.f;

    const float am0 = amask[(size_t)b * Tt + q0 + w * 16 + g];
    const float am1 = amask[(size_t)b * Tt + q0 + w * 16 + g + 8];
    const int qg0 = q0 + w * 16 + g;
    const int qg1 = qg0 + 8;

    int srow[2], scw[2];
#pragma unroll
    for (int r = 0; r < 2; r++) { int idx = r*256+tid; srow[r]=idx>>3; scw[r]=(idx&7)<<2; }

    // prologue: stage tile tstart into buffer 0
    {
        const uint32_t* kp = g_kh + ((size_t)b * Tt + tstart * 64) * 32;
        const uint32_t* vp = g_vh + ((size_t)b * Tt + tstart * 64) * 32;
        uint32_t* Kd = smw + OKV;
        uint32_t* Vd = smw + OKV + 2304;
#pragma unroll
        for (int r = 0; r < 2; r++) {
            *(uint4*)&Kd[srow[r] * 36 + scw[r]] = *(const uint4*)&kp[srow[r] * 32 + scw[r]];
            *(uint4*)&Vd[srow[r] * 36 + scw[r]] = *(const uint4*)&vp[srow[r] * 32 + scw[r]];
        }
    }
    __syncthreads();

    for (int tt = tstart; tt < tend; tt++) {
        const int cur = (tt - tstart) & 1;
        const int j0 = tt * 64;
        const bool more = (tt + 1 < tend);
        const bool interior = (j0 + 63 <= q0);

        uint4 stK[2], stV[2];
        if (more) {
            const uint32_t* kp = g_kh + ((size_t)b * Tt + (tt + 1) * 64) * 32;
            const uint32_t* vp = g_vh + ((size_t)b * Tt + (tt + 1) * 64) * 32;
#pragma unroll
            for (int r = 0; r < 2; r++) {
                stK[r] = *(const uint4*)&kp[srow[r] * 32 + scw[r]];
                stV[r] = *(const uint4*)&vp[srow[r] * 32 + scw[r]];
            }
        }

        const uint32_t sbq = sb;
        const uint32_t sbk = sb + (uint32_t)((OKV + cur * 4608) * 4);
        const uint32_t sbv = sb + (uint32_t)((OKV + cur * 4608 + 2304) * 4);

        // S = Q K^T (fragments via ldmatrix)
        float c[8][4];
#pragma unroll
        for (int f = 0; f < 8; f++)
#pragma unroll
            for (int r = 0; r < 4; r++) c[f][r] = 0.f;
#pragma unroll
        for (int ks = 0; ks < 4; ks++) {
            uint32_t a[4];
            ldsm_x4(a[0], a[1], a[2], a[3],
                    sbq + (uint32_t)((a_lrow * 36 + ks * 8 + a_kh) * 4));
            uint32_t bf[8][2];
#pragma unroll
            for (int p = 0; p < 4; p++) {
                uint32_t d0, d1, d2, d3;
                ldsm_x4(d0, d1, d2, d3,
                        sbk + (uint32_t)(((b_lrow + p * 16) * 36 + ks * 8 + b_kh) * 4));
                bf[2*p][0] = d0; bf[2*p][1] = d1;
                bf[2*p+1][0] = d2; bf[2*p+1][1] = d3;
            }
#pragma unroll
            for (int f = 0; f < 8; f++)
                mma_fp16(c[f], a, bf[f][0], bf[f][1]);
        }

        // masks
        float mx0 = -INFINITY, mx1 = -INFINITY;
        if (interior) {
#pragma unroll
            for (int f = 0; f < 8; f++) {
                float v0 = c[f][0] * 0.125f * am0;
                float v1 = c[f][1] * 0.125f * am0;
                float v2 = c[f][2] * 0.125f * am1;
                float v3 = c[f][3] * 0.125f * am1;
                if (v0 == 0.f) v0 = -INFINITY;
                if (v1 == 0.f) v1 = -INFINITY;
                if (v2 == 0.f) v2 = -INFINITY;
                if (v3 == 0.f) v3 = -INFINITY;
                c[f][0] = v0; c[f][1] = v1; c[f][2] = v2; c[f][3] = v3;
                mx0 = fmaxf(mx0, fmaxf(v0, v1));
                mx1 = fmaxf(mx1, fmaxf(v2, v3));
            }
        } else {
#pragma unroll
            for (int f = 0; f < 8; f++) {
                int col = j0 + f * 8 + t * 2;
                float v0 = c[f][0] * 0.125f * am0;
                float v1 = c[f][1] * 0.125f * am0;
                float v2 = c[f][2] * 0.125f * am1;
                float v3 = c[f][3] * 0.125f * am1;
                if (v0 == 0.f || col     > qg0) v0 = -INFINITY;
                if (v1 == 0.f || col + 1 > qg0) v1 = -INFINITY;
                if (v2 == 0.f || col     > qg1) v2 = -INFINITY;
                if (v3 == 0.f || col + 1 > qg1) v3 = -INFINITY;
                c[f][0] = v0; c[f][1] = v1; c[f][2] = v2; c[f][3] = v3;
                mx0 = fmaxf(mx0, fmaxf(v0, v1));
                mx1 = fmaxf(mx1, fmaxf(v2, v3));
            }
        }
        mx0 = fmaxf(mx0, __shfl_xor_sync(0xffffffffu, mx0, 1));
        mx0 = fmaxf(mx0, __shfl_xor_sync(0xffffffffu, mx0, 2));
        mx1 = fmaxf(mx1, __shfl_xor_sync(0xffffffffu, mx1, 1));
        mx1 = fmaxf(mx1, __shfl_xor_sync(0xffffffffu, mx1, 2));

        float mn0 = fmaxf(m0, mx0), mn1 = fmaxf(m1, mx1);
        float alpha0, alpha1, ls0 = 0.f, ls1 = 0.f;
        uint32_t p01[8], p23[8];
        if (mn0 == -INFINITY) {
            alpha0 = 1.f;
#pragma unroll
            for (int f = 0; f < 8; f++) { c[f][0] = 0.f; c[f][1] = 0.f; }
        } else {
            alpha0 = __expf(m0 - mn0);
#pragma unroll
            for (int f = 0; f < 8; f++) {
                c[f][0] = __expf(c[f][0] - mn0);
                c[f][1] = __expf(c[f][1] - mn0);
                ls0 += c[f][0] + c[f][1];
            }
        }
        if (mn1 == -INFINITY) {
            alpha1 = 1.f;
#pragma unroll
            for (int f = 0; f < 8; f++) { c[f][2] = 0.f; c[f][3] = 0.f; }
        } else {
            alpha1 = __expf(m1 - mn1);
#pragma unroll
            for (int f = 0; f < 8; f++) {
                c[f][2] = __expf(c[f][2] - mn1);
                c[f][3] = __expf(c[f][3] - mn1);
                ls1 += c[f][2] + c[f][3];
            }
        }
        m0 = mn0; m1 = mn1;
        ls0 += __shfl_xor_sync(0xffffffffu, ls0, 1);
        ls0 += __shfl_xor_sync(0xffffffffu, ls0, 2);
        ls1 += __shfl_xor_sync(0xffffffffu, ls1, 1);
        ls1 += __shfl_xor_sync(0xffffffffu, ls1, 2);
        l0 = l0 * alpha0 + ls0;
        l1 = l1 * alpha1 + ls1;

#pragma unroll
        for (int f = 0; f < 8; f++) {
            p01[f] = h2pack(c[f][0], c[f][1]);
            p23[f] = h2pack(c[f][2], c[f][3]);
            o[f][0] *= alpha0; o[f][1] *= alpha0;
            o[f][2] *= alpha1; o[f][3] *= alpha1;
        }

        // O += P V
        const int vrow = (lane & 15);
        const int vcb  = ((lane >> 4) & 1) << 2;
#pragma unroll
        for (int ss = 0; ss < 4; ss++) {
            uint32_t a[4];
            a[0] = p01[2 * ss];     a[1] = p23[2 * ss];
            a[2] = p01[2 * ss + 1]; a[3] = p23[2 * ss + 1];
#pragma unroll
            for (int p = 0; p < 4; p++) {
                uint32_t d0, d1, d2, d3;
                ldsm_x4_t(d0, d1, d2, d3,
                          sbv + (uint32_t)((((ss * 16 + vrow) * 36) + p * 8 + vcb) * 4));
                mma_fp16(o[2 * p],     a, d0, d1);
                mma_fp16(o[2 * p + 1], a, d2, d3);
            }
        }

        if (more) {
            uint32_t* Kd = smw + OKV + (cur ^ 1) * 4608;
            uint32_t* Vd = Kd + 2304;
#pragma unroll
            for (int r = 0; r < 2; r++) {
                *(uint4*)&Kd[srow[r] * 36 + scw[r]] = stK[r];
                *(uint4*)&Vd[srow[r] * 36 + scw[r]] = stV[r];
            }
        }
        __syncthreads();
    }

    // epilogue: write unnormalized partials into slot `part`
    float* po0 = g_po + ((size_t)part * M_TOT + (size_t)b * Tt + qg0) * 64;
    float* po1 = g_po + ((size_t)part * M_TOT + (size_t)b * Tt + qg1) * 64;
#pragma unroll
    for (int f = 0; f < 8; f++) {
        int col = f * 8 + t * 2;
        *(float2*)(po0 + col) = make_float2(o[f][0], o[f][1]);
        *(float2*)(po1 + col) = make_float2(o[f][2], o[f][3]);
    }
    if (t == 0) {
        size_t r0 = (size_t)part * M_TOT + (size_t)b * Tt + qg0;
        size_t r1 = (size_t)part * M_TOT + (size_t)b * Tt + qg1;
        g_pm[r0] = m0; g_pl[r0] = l0;
        g_pm[r1] = m1; g_pl[r1] = l1;
    }
}

// ---------------------------------------------------------------------------
// Kernel 3: combine up to 4 splits
// ---------------------------------------------------------------------------
__global__ void combine(float* __restrict__ out)
{
    int idx = blockIdx.x * 256 + threadIdx.x;
    int row = idx >> 4;
    int c4  = (idx & 15) << 2;
    int iq  = (row & (Tt - 1)) >> 7;
    int ns  = (iq >= 12) ? 4 : (iq >= 8) ? 3 : (iq >= 4) ? 2 : 1;

    float mv[4], lv[4];
    float M = -INFINITY;
    for (int s = 0; s < ns; s++) {
        mv[s] = g_pm[(size_t)s * M_TOT + row];
        lv[s] = g_pl[(size_t)s * M_TOT + row];
        M = fmaxf(M, mv[s]);
    }
    float l = 0.f;
    float wv[4];
    for (int s = 0; s < ns; s++) {
        wv[s] = (mv[s] == -INFINITY) ? 0.f : __expf(mv[s] - M);
        l += lv[s] * wv[s];
    }
    float inv = (l > 0.f) ? (1.f / l) : 0.f;

    float4 acc = make_float4(0.f, 0.f, 0.f, 0.f);
    for (int s = 0; s < ns; s++) {
        float4 a = *(const float4*)&g_po[((size_t)s * M_TOT + row) * 64 + c4];
        acc.x += a.x * wv[s]; acc.y += a.y * wv[s];
        acc.z += a.z * wv[s]; acc.w += a.w * wv[s];
    }
    acc.x *= inv; acc.y *= inv; acc.z *= inv; acc.w *= inv;
    *(float4*)&out[(size_t)row * 64 + c4] = acc;
}

// ---------------------------------------------------------------------------
extern "C" void kernel_launch(void* const* d_in, const int* in_sizes, int n_in,
                              void* d_out, int out_size)
{
    const float* x  = (const float*)d_in[0];
    const float* am = (const float*)d_in[1];
    const float* Wq = (const float*)d_in[2];
    const float* Wk = (const float*)d_in[3];
    const float* Wv = (const float*)d_in[4];
    float*       out = (float*)d_out;

    wtrans<<<36, 256>>>(Wq, Wk, Wv);
    xcvt<<<(M_TOT * Cc / 8) / 256, 256>>>(x);

    cudaFuncSetAttribute(qkv_h,
                         cudaFuncAttributeMaxDynamicSharedMemorySize, QKV_SMEM);
    qkv_h<<<M_TOT / 128, 256, QKV_SMEM>>>();

    cudaFuncSetAttribute(attn_mma,
                         cudaFuncAttributeMaxDynamicSharedMemorySize, ATTN_SMEM);
    dim3 g2(40, Bb);
    attn_mma<<<g2, 256, ATTN_SMEM>>>(am);

    combine<<<(M_TOT * 16) / 256, 256>>>(out);
}

// round 15
// speedup vs baseline: 1.2207x; 1.1276x over previous
#include <cuda_runtime.h>
#include <cuda_fp16.h>
#include <math.h>
#include <stdint.h>

#define Bb 8
#define Tt 2048
#define Cc 768
#define Hh 64
#define M_TOT (Bb*Tt)

// fp16 scratch (half2 packed in uint32)
__device__ uint32_t g_wth[192*Cc/2];     // fused transposed weights fp16 [n][k]
__device__ uint32_t g_qh[M_TOT*32];      // q fp16 [row][h]
__device__ uint32_t g_kh[M_TOT*32];
__device__ uint32_t g_vh[M_TOT*32];
// split-KV partials (up to 4 splits)
__device__ float g_po[4 * M_TOT * 64];
__device__ float g_pm[4 * M_TOT];
__device__ float g_pl[4 * M_TOT];

// ---------------------------------------------------------------------------
// helpers
// ---------------------------------------------------------------------------
__device__ __forceinline__ void mma_fp16(float* d, const uint32_t* a,
                                         uint32_t b0, uint32_t b1) {
    asm volatile(
        "mma.sync.aligned.m16n8k16.row.col.f32.f16.f16.f32 "
        "{%0,%1,%2,%3}, {%4,%5,%6,%7}, {%8,%9}, {%0,%1,%2,%3};"
        : "+f"(d[0]), "+f"(d[1]), "+f"(d[2]), "+f"(d[3])
        : "r"(a[0]), "r"(a[1]), "r"(a[2]), "r"(a[3]), "r"(b0), "r"(b1));
}

__device__ __forceinline__ void ldsm_x4(uint32_t& d0, uint32_t& d1,
                                        uint32_t& d2, uint32_t& d3,
                                        uint32_t saddr) {
    asm volatile("ldmatrix.sync.aligned.m8n8.x4.shared.b16 {%0,%1,%2,%3}, [%4];"
                 : "=r"(d0), "=r"(d1), "=r"(d2), "=r"(d3) : "r"(saddr));
}

__device__ __forceinline__ void ldsm_x4_t(uint32_t& d0, uint32_t& d1,
                                          uint32_t& d2, uint32_t& d3,
                                          uint32_t saddr) {
    asm volatile("ldmatrix.sync.aligned.m8n8.x4.trans.shared.b16 {%0,%1,%2,%3}, [%4];"
                 : "=r"(d0), "=r"(d1), "=r"(d2), "=r"(d3) : "r"(saddr));
}

__device__ __forceinline__ uint32_t smem_u32(const void* p) {
    uint32_t a;
    asm("{ .reg .u64 t; cvta.to.shared.u64 t, %1; cvt.u32.u64 %0, t; }"
        : "=r"(a) : "l"(p));
    return a;
}

__device__ __forceinline__ uint32_t h2pack(float x, float y) {
    __half2 h = __floats2half2_rn(x, y);
    return *(uint32_t*)&h;
}

// ---------------------------------------------------------------------------
// Kernel 0: transpose+fuse weights -> fp16 g_wth[n][k] (coalesced)
// ---------------------------------------------------------------------------
__global__ void wtrans(const float* __restrict__ Wq,
                       const float* __restrict__ Wk,
                       const float* __restrict__ Wv)
{
    __shared__ float s[64][65];
    const int wsel = blockIdx.x / 12;
    const int k0   = (blockIdx.x % 12) * 64;
    const float* W = (wsel == 0) ? Wq : (wsel == 1 ? Wk : Wv);
    const int tid = threadIdx.x;

#pragma unroll
    for (int r = 0; r < 16; r++) {
        int idx = r * 256 + tid;
        int k = idx >> 6, h = idx & 63;
        s[k][h] = W[(size_t)(k0 + k) * Hh + h];
    }
    __syncthreads();

#pragma unroll
    for (int r = 0; r < 8; r++) {
        int idx = r * 256 + tid;
        int h = idx >> 5, kw = idx & 31;
        g_wth[(size_t)(wsel * 64 + h) * (Cc / 2) + (k0 >> 1) + kw] =
            h2pack(s[2 * kw][h], s[2 * kw + 1][h]);
    }
}

// ---------------------------------------------------------------------------
// Kernel 1: QKV projection, fp32 x loaded directly (inline fp16 convert on
// the A path — xcvt kernel eliminated; A-tiles partition x exactly once).
// CTA tile 128(M) x 192(N fused), BK=32, double-buffered.
// ---------------------------------------------------------------------------
#define BKh 32
#define NCH (Cc / BKh)
#define W_A 0                  // [2][128*20] words
#define W_B 5120               // [2][192*20] words
#define QKV_SMEM (12800 * 4)   // 51200 B

__global__ __launch_bounds__(256) void qkv_h(const float* __restrict__ x)
{
    extern __shared__ uint32_t smw[];
    const uint32_t sb = smem_u32(smw);

    const int tid  = threadIdx.x;
    const int lane = tid & 31, wid = tid >> 5;
    const int m0   = blockIdx.x * 128;
    const int g    = lane >> 2, tig = lane & 3;
    const int wm   = wid & 3,  wn  = wid >> 2;

    // A: 2 rows/thread, fp32 source (8 floats -> 1 uint4 of half2)
    int rowA[2], cwA[2], rowB[3], cwB[3];
#pragma unroll
    for (int r = 0; r < 2; r++) { int idx = r*256+tid; rowA[r]=idx>>2; cwA[r]=(idx&3)<<2; }
#pragma unroll
    for (int r = 0; r < 3; r++) { int idx = r*256+tid; rowB[r]=idx>>2; cwB[r]=(idx&3)<<2; }

    const int a_lrow = wm * 32 + (lane & 15);
    const int a_kh   = ((lane >> 4) & 1) << 2;
    const int b_lrow = wn * 96 + ((lane >> 4) & 1) * 8 + (lane & 7);
    const int b_kh   = ((lane >> 3) & 1) << 2;

    float acc[2][12][4];
#pragma unroll
    for (int i = 0; i < 2; i++)
#pragma unroll
        for (int j = 0; j < 12; j++)
#pragma unroll
            for (int r = 0; r < 4; r++) acc[i][j][r] = 0.f;

    // prologue: chunk 0 -> buffer 0
#pragma unroll
    for (int r = 0; r < 2; r++) {
        const float* xp = x + (size_t)(m0 + rowA[r]) * Cc + 2 * cwA[r];
        float4 f0 = *(const float4*)xp;
        float4 f1 = *(const float4*)(xp + 4);
        *(uint4*)&smw[W_A + rowA[r] * 20 + cwA[r]] =
            make_uint4(h2pack(f0.x, f0.y), h2pack(f0.z, f0.w),
                       h2pack(f1.x, f1.y), h2pack(f1.z, f1.w));
    }
#pragma unroll
    for (int r = 0; r < 3; r++)
        *(uint4*)&smw[W_B + rowB[r] * 20 + cwB[r]] =
            *(const uint4*)&g_wth[(size_t)rowB[r] * (Cc/2) + cwB[r]];
    __syncthreads();

    for (int t = 0; t < NCH; t++) {
        const int buf = t & 1;
        float4 stA0[2], stA1[2];
        uint4 stB[3];
        if (t + 1 < NCH) {
            const int k0f = (t + 1) * BKh;   // float offset
            const int k0w = (t + 1) * (BKh / 2);
#pragma unroll
            for (int r = 0; r < 2; r++) {
                const float* xp = x + (size_t)(m0 + rowA[r]) * Cc + k0f + 2 * cwA[r];
                stA0[r] = *(const float4*)xp;
                stA1[r] = *(const float4*)(xp + 4);
            }
#pragma unroll
            for (int r = 0; r < 3; r++)
                stB[r] = *(const uint4*)&g_wth[(size_t)rowB[r] * (Cc/2) + k0w + cwB[r]];
        }

        const uint32_t Abase = sb + (W_A + buf * 2560) * 4;
        const uint32_t Bbase = sb + (W_B + buf * 3840) * 4;

#pragma unroll
        for (int kk2 = 0; kk2 < 16; kk2 += 8) {
            uint32_t a[2][4];
#pragma unroll
            for (int i = 0; i < 2; i++)
                ldsm_x4(a[i][0], a[i][1], a[i][2], a[i][3],
                        Abase + (uint32_t)(((a_lrow + i * 16) * 20 + kk2 + a_kh) * 4));
            uint32_t bf[12][2];
#pragma unroll
            for (int p = 0; p < 6; p++) {
                uint32_t d0, d1, d2, d3;
                ldsm_x4(d0, d1, d2, d3,
                        Bbase + (uint32_t)(((b_lrow + p * 16) * 20 + kk2 + b_kh) * 4));
                bf[2*p][0] = d0; bf[2*p][1] = d1;
                bf[2*p+1][0] = d2; bf[2*p+1][1] = d3;
            }
#pragma unroll
            for (int j = 0; j < 12; j++) {
                mma_fp16(acc[0][j], a[0], bf[j][0], bf[j][1]);
                mma_fp16(acc[1][j], a[1], bf[j][0], bf[j][1]);
            }
        }

        if (t + 1 < NCH) {
            uint32_t* Ad = smw + W_A + (buf ^ 1) * 2560;
            uint32_t* Bd = smw + W_B + (buf ^ 1) * 3840;
#pragma unroll
            for (int r = 0; r < 2; r++)
                *(uint4*)&Ad[rowA[r] * 20 + cwA[r]] =
                    make_uint4(h2pack(stA0[r].x, stA0[r].y), h2pack(stA0[r].z, stA0[r].w),
                               h2pack(stA1[r].x, stA1[r].y), h2pack(stA1[r].z, stA1[r].w));
#pragma unroll
            for (int r = 0; r < 3; r++)
                *(uint4*)&Bd[rowB[r] * 20 + cwB[r]] = stB[r];
        }
        __syncthreads();
    }

#pragma unroll
    for (int i = 0; i < 2; i++) {
        int r0 = m0 + wm * 32 + i * 16 + g;
#pragma unroll
        for (int j = 0; j < 12; j++) {
            int c = wn * 96 + j * 8 + tig * 2;
            uint32_t* op = (c < 64) ? g_qh : (c < 128 ? g_kh : g_vh);
            int oc = (c & 63) >> 1;
            op[(size_t)r0 * 32 + oc]       = h2pack(acc[i][j][0], acc[i][j][1]);
            op[(size_t)(r0 + 8) * 32 + oc] = h2pack(acc[i][j][2], acc[i][j][3]);
        }
    }
}

// ---------------------------------------------------------------------------
// Kernel 2: causal flash attention, adaptive split-KV, ldmatrix S-path
// (unchanged — measured ~31-32us).
// ---------------------------------------------------------------------------
#define OQ  0
#define OKV 4608
#define ATTN_SMEM (13824 * 4)

__global__ __launch_bounds__(256, 2) void attn_mma(
    const float* __restrict__ amask)
{
    extern __shared__ uint32_t smw[];
    uint32_t* Qs = smw + OQ;
    const uint32_t sb = smem_u32(smw);

    const int b   = blockIdx.y;
    const int x   = blockIdx.x;
    int iq, part, ns;
    if (x < 16)      { iq = 15 - (x >> 2);        part = x & 3;        ns = 4; }
    else if (x < 28) { iq = 11 - (x - 16) / 3;    part = (x - 16) % 3; ns = 3; }
    else if (x < 36) { iq = 7  - ((x - 28) >> 1); part = (x - 28) & 1; ns = 2; }
    else             { iq = 3  - (x - 36);        part = 0;            ns = 1; }

    const int q0  = iq * 128;
    const int ntiles = 2 * iq + 2;
    const int base = ntiles / ns, rem = ntiles % ns;
    const int tstart = part * base + min(part, rem);
    const int tend   = tstart + base + (part < rem ? 1 : 0);

    const int tid = threadIdx.x;
    const int lane = tid & 31, w = tid >> 5;
    const int g = lane >> 2, t = lane & 3;

    const int a_lrow = w * 16 + (lane & 15);
    const int a_kh   = ((lane >> 4) & 1) << 2;
    const int b_lrow = ((lane >> 4) & 1) * 8 + (lane & 7);
    const int b_kh   = ((lane >> 3) & 1) << 2;

    // stage Q
    const uint32_t* qp = g_qh + ((size_t)b * Tt + q0) * 32;
#pragma unroll
    for (int r = 0; r < 4; r++) {
        int idx = r * 256 + tid;
        int row = idx >> 3, cw = (idx & 7) << 2;
        *(uint4*)&Qs[row * 36 + cw] = *(const uint4*)&qp[row * 32 + cw];
    }

    float m0 = -INFINITY, m1 = -INFINITY, l0 = 0.f, l1 = 0.f;
    float o[8][4];
#pragma unroll
    for (int f = 0; f < 8; f++)
#pragma unroll
        for (int r = 0; r < 4; r++) o[f][r] = 0.f;

    const float am0 = amask[(size_t)b * Tt + q0 + w * 16 + g];
    const float am1 = amask[(size_t)b * Tt + q0 + w * 16 + g + 8];
    const int qg0 = q0 + w * 16 + g;
    const int qg1 = qg0 + 8;

    int srow[2], scw[2];
#pragma unroll
    for (int r = 0; r < 2; r++) { int idx = r*256+tid; srow[r]=idx>>3; scw[r]=(idx&7)<<2; }

    // prologue: stage tile tstart into buffer 0
    {
        const uint32_t* kp = g_kh + ((size_t)b * Tt + tstart * 64) * 32;
        const uint32_t* vp = g_vh + ((size_t)b * Tt + tstart * 64) * 32;
        uint32_t* Kd = smw + OKV;
        uint32_t* Vd = smw + OKV + 2304;
#pragma unroll
        for (int r = 0; r < 2; r++) {
            *(uint4*)&Kd[srow[r] * 36 + scw[r]] = *(const uint4*)&kp[srow[r] * 32 + scw[r]];
            *(uint4*)&Vd[srow[r] * 36 + scw[r]] = *(const uint4*)&vp[srow[r] * 32 + scw[r]];
        }
    }
    __syncthreads();

    for (int tt = tstart; tt < tend; tt++) {
        const int cur = (tt - tstart) & 1;
        const int j0 = tt * 64;
        const bool more = (tt + 1 < tend);
        const bool interior = (j0 + 63 <= q0);

        uint4 stK[2], stV[2];
        if (more) {
            const uint32_t* kp = g_kh + ((size_t)b * Tt + (tt + 1) * 64) * 32;
            const uint32_t* vp = g_vh + ((size_t)b * Tt + (tt + 1) * 64) * 32;
#pragma unroll
            for (int r = 0; r < 2; r++) {
                stK[r] = *(const uint4*)&kp[srow[r] * 32 + scw[r]];
                stV[r] = *(const uint4*)&vp[srow[r] * 32 + scw[r]];
            }
        }

        const uint32_t sbq = sb;
        const uint32_t sbk = sb + (uint32_t)((OKV + cur * 4608) * 4);
        const uint32_t sbv = sb + (uint32_t)((OKV + cur * 4608 + 2304) * 4);

        // S = Q K^T (fragments via ldmatrix)
        float c[8][4];
#pragma unroll
        for (int f = 0; f < 8; f++)
#pragma unroll
            for (int r = 0; r < 4; r++) c[f][r] = 0.f;
#pragma unroll
        for (int ks = 0; ks < 4; ks++) {
            uint32_t a[4];
            ldsm_x4(a[0], a[1], a[2], a[3],
                    sbq + (uint32_t)((a_lrow * 36 + ks * 8 + a_kh) * 4));
            uint32_t bf[8][2];
#pragma unroll
            for (int p = 0; p < 4; p++) {
                uint32_t d0, d1, d2, d3;
                ldsm_x4(d0, d1, d2, d3,
                        sbk + (uint32_t)(((b_lrow + p * 16) * 36 + ks * 8 + b_kh) * 4));
                bf[2*p][0] = d0; bf[2*p][1] = d1;
                bf[2*p+1][0] = d2; bf[2*p+1][1] = d3;
            }
#pragma unroll
            for (int f = 0; f < 8; f++)
                mma_fp16(c[f], a, bf[f][0], bf[f][1]);
        }

        // masks
        float mx0 = -INFINITY, mx1 = -INFINITY;
        if (interior) {
#pragma unroll
            for (int f = 0; f < 8; f++) {
                float v0 = c[f][0] * 0.125f * am0;
                float v1 = c[f][1] * 0.125f * am0;
                float v2 = c[f][2] * 0.125f * am1;
                float v3 = c[f][3] * 0.125f * am1;
                if (v0 == 0.f) v0 = -INFINITY;
                if (v1 == 0.f) v1 = -INFINITY;
                if (v2 == 0.f) v2 = -INFINITY;
                if (v3 == 0.f) v3 = -INFINITY;
                c[f][0] = v0; c[f][1] = v1; c[f][2] = v2; c[f][3] = v3;
                mx0 = fmaxf(mx0, fmaxf(v0, v1));
                mx1 = fmaxf(mx1, fmaxf(v2, v3));
            }
        } else {
#pragma unroll
            for (int f = 0; f < 8; f++) {
                int col = j0 + f * 8 + t * 2;
                float v0 = c[f][0] * 0.125f * am0;
                float v1 = c[f][1] * 0.125f * am0;
                float v2 = c[f][2] * 0.125f * am1;
                float v3 = c[f][3] * 0.125f * am1;
                if (v0 == 0.f || col     > qg0) v0 = -INFINITY;
                if (v1 == 0.f || col + 1 > qg0) v1 = -INFINITY;
                if (v2 == 0.f || col     > qg1) v2 = -INFINITY;
                if (v3 == 0.f || col + 1 > qg1) v3 = -INFINITY;
                c[f][0] = v0; c[f][1] = v1; c[f][2] = v2; c[f][3] = v3;
                mx0 = fmaxf(mx0, fmaxf(v0, v1));
                mx1 = fmaxf(mx1, fmaxf(v2, v3));
            }
        }
        mx0 = fmaxf(mx0, __shfl_xor_sync(0xffffffffu, mx0, 1));
        mx0 = fmaxf(mx0, __shfl_xor_sync(0xffffffffu, mx0, 2));
        mx1 = fmaxf(mx1, __shfl_xor_sync(0xffffffffu, mx1, 1));
        mx1 = fmaxf(mx1, __shfl_xor_sync(0xffffffffu, mx1, 2));

        float mn0 = fmaxf(m0, mx0), mn1 = fmaxf(m1, mx1);
        float alpha0, alpha1, ls0 = 0.f, ls1 = 0.f;
        uint32_t p01[8], p23[8];
        if (mn0 == -INFINITY) {
            alpha0 = 1.f;
#pragma unroll
            for (int f = 0; f < 8; f++) { c[f][0] = 0.f; c[f][1] = 0.f; }
        } else {
            alpha0 = __expf(m0 - mn0);
#pragma unroll
            for (int f = 0; f < 8; f++) {
                c[f][0] = __expf(c[f][0] - mn0);
                c[f][1] = __expf(c[f][1] - mn0);
                ls0 += c[f][0] + c[f][1];
            }
        }
        if (mn1 == -INFINITY) {
            alpha1 = 1.f;
#pragma unroll
            for (int f = 0; f < 8; f++) { c[f][2] = 0.f; c[f][3] = 0.f; }
        } else {
            alpha1 = __expf(m1 - mn1);
#pragma unroll
            for (int f = 0; f < 8; f++) {
                c[f][2] = __expf(c[f][2] - mn1);
                c[f][3] = __expf(c[f][3] - mn1);
                ls1 += c[f][2] + c[f][3];
            }
        }
        m0 = mn0; m1 = mn1;
        ls0 += __shfl_xor_sync(0xffffffffu, ls0, 1);
        ls0 += __shfl_xor_sync(0xffffffffu, ls0, 2);
        ls1 += __shfl_xor_sync(0xffffffffu, ls1, 1);
        ls1 += __shfl_xor_sync(0xffffffffu, ls1, 2);
        l0 = l0 * alpha0 + ls0;
        l1 = l1 * alpha1 + ls1;

#pragma unroll
        for (int f = 0; f < 8; f++) {
            p01[f] = h2pack(c[f][0], c[f][1]);
            p23[f] = h2pack(c[f][2], c[f][3]);
            o[f][0] *= alpha0; o[f][1] *= alpha0;
            o[f][2] *= alpha1; o[f][3] *= alpha1;
        }

        // O += P V
        const int vrow = (lane & 15);
        const int vcb  = ((lane >> 4) & 1) << 2;
#pragma unroll
        for (int ss = 0; ss < 4; ss++) {
            uint32_t a[4];
            a[0] = p01[2 * ss];     a[1] = p23[2 * ss];
            a[2] = p01[2 * ss + 1]; a[3] = p23[2 * ss + 1];
#pragma unroll
            for (int p = 0; p < 4; p++) {
                uint32_t d0, d1, d2, d3;
                ldsm_x4_t(d0, d1, d2, d3,
                          sbv + (uint32_t)((((ss * 16 + vrow) * 36) + p * 8 + vcb) * 4));
                mma_fp16(o[2 * p],     a, d0, d1);
                mma_fp16(o[2 * p + 1], a, d2, d3);
            }
        }

        if (more) {
            uint32_t* Kd = smw + OKV + (cur ^ 1) * 4608;
            uint32_t* Vd = Kd + 2304;
#pragma unroll
            for (int r = 0; r < 2; r++) {
                *(uint4*)&Kd[srow[r] * 36 + scw[r]] = stK[r];
                *(uint4*)&Vd[srow[r] * 36 + scw[r]] = stV[r];
            }
        }
        __syncthreads();
    }

    // epilogue: write unnormalized partials into slot `part`
    float* po0 = g_po + ((size_t)part * M_TOT + (size_t)b * Tt + qg0) * 64;
    float* po1 = g_po + ((size_t)part * M_TOT + (size_t)b * Tt + qg1) * 64;
#pragma unroll
    for (int f = 0; f < 8; f++) {
        int col = f * 8 + t * 2;
        *(float2*)(po0 + col) = make_float2(o[f][0], o[f][1]);
        *(float2*)(po1 + col) = make_float2(o[f][2], o[f][3]);
    }
    if (t == 0) {
        size_t r0 = (size_t)part * M_TOT + (size_t)b * Tt + qg0;
        size_t r1 = (size_t)part * M_TOT + (size_t)b * Tt + qg1;
        g_pm[r0] = m0; g_pl[r0] = l0;
        g_pm[r1] = m1; g_pl[r1] = l1;
    }
}

// ---------------------------------------------------------------------------
// Kernel 3: combine up to 4 splits
// ---------------------------------------------------------------------------
__global__ void combine(float* __restrict__ out)
{
    int idx = blockIdx.x * 256 + threadIdx.x;
    int row = idx >> 4;
    int c4  = (idx & 15) << 2;
    int iq  = (row & (Tt - 1)) >> 7;
    int ns  = (iq >= 12) ? 4 : (iq >= 8) ? 3 : (iq >= 4) ? 2 : 1;

    float mv[4], lv[4];
    float M = -INFINITY;
    for (int s = 0; s < ns; s++) {
        mv[s] = g_pm[(size_t)s * M_TOT + row];
        lv[s] = g_pl[(size_t)s * M_TOT + row];
        M = fmaxf(M, mv[s]);
    }
    float l = 0.f;
    float wv[4];
    for (int s = 0; s < ns; s++) {
        wv[s] = (mv[s] == -INFINITY) ? 0.f : __expf(mv[s] - M);
        l += lv[s] * wv[s];
    }
    float inv = (l > 0.f) ? (1.f / l) : 0.f;

    float4 acc = make_float4(0.f, 0.f, 0.f, 0.f);
    for (int s = 0; s < ns; s++) {
        float4 a = *(const float4*)&g_po[((size_t)s * M_TOT + row) * 64 + c4];
        acc.x += a.x * wv[s]; acc.y += a.y * wv[s];
        acc.z += a.z * wv[s]; acc.w += a.w * wv[s];
    }
    acc.x *= inv; acc.y *= inv; acc.z *= inv; acc.w *= inv;
    *(float4*)&out[(size_t)row * 64 + c4] = acc;
}

// ---------------------------------------------------------------------------
extern "C" void kernel_launch(void* const* d_in, const int* in_sizes, int n_in,
                              void* d_out, int out_size)
{
    const float* x  = (const float*)d_in[0];
    const float* am = (const float*)d_in[1];
    const float* Wq = (const float*)d_in[2];
    const float* Wk = (const float*)d_in[3];
    const float* Wv = (const float*)d_in[4];
    float*       out = (float*)d_out;

    wtrans<<<36, 256>>>(Wq, Wk, Wv);

    cudaFuncSetAttribute(qkv_h,
                         cudaFuncAttributeMaxDynamicSharedMemorySize, QKV_SMEM);
    qkv_h<<<M_TOT / 128, 256, QKV_SMEM>>>(x);

    cudaFuncSetAttribute(attn_mma,
                         cudaFuncAttributeMaxDynamicSharedMemorySize, ATTN_SMEM);
    dim3 g2(40, Bb);
    attn_mma<<<g2, 256, ATTN_SMEM>>>(am);

    combine<<<(M_TOT * 16) / 256, 256>>>(out);
}

// round 16
// speedup vs baseline: 1.2661x; 1.0372x over previous
#include <cuda_runtime.h>
#include <cuda_fp16.h>
#include <math.h>
#include <stdint.h>

#define Bb 8
#define Tt 2048
#define Cc 768
#define Hh 64
#define M_TOT (Bb*Tt)

// fp16 scratch (half2 packed in uint32)
__device__ uint32_t g_wth[192*Cc/2];     // fused transposed weights fp16 [n][k]
__device__ uint32_t g_qh[M_TOT*32];      // q fp16 [row][h]
__device__ uint32_t g_kh[M_TOT*32];
__device__ uint32_t g_vh[M_TOT*32];
// split-KV partials (up to 4 splits)
__device__ float g_po[4 * M_TOT * 64];
__device__ float g_pm[4 * M_TOT];
__device__ float g_pl[4 * M_TOT];

// ---------------------------------------------------------------------------
// helpers
// ---------------------------------------------------------------------------
__device__ __forceinline__ void mma_fp16(float* d, const uint32_t* a,
                                         uint32_t b0, uint32_t b1) {
    asm volatile(
        "mma.sync.aligned.m16n8k16.row.col.f32.f16.f16.f32 "
        "{%0,%1,%2,%3}, {%4,%5,%6,%7}, {%8,%9}, {%0,%1,%2,%3};"
        : "+f"(d[0]), "+f"(d[1]), "+f"(d[2]), "+f"(d[3])
        : "r"(a[0]), "r"(a[1]), "r"(a[2]), "r"(a[3]), "r"(b0), "r"(b1));
}

__device__ __forceinline__ void ldsm_x4(uint32_t& d0, uint32_t& d1,
                                        uint32_t& d2, uint32_t& d3,
                                        uint32_t saddr) {
    asm volatile("ldmatrix.sync.aligned.m8n8.x4.shared.b16 {%0,%1,%2,%3}, [%4];"
                 : "=r"(d0), "=r"(d1), "=r"(d2), "=r"(d3) : "r"(saddr));
}

__device__ __forceinline__ void ldsm_x4_t(uint32_t& d0, uint32_t& d1,
                                          uint32_t& d2, uint32_t& d3,
                                          uint32_t saddr) {
    asm volatile("ldmatrix.sync.aligned.m8n8.x4.trans.shared.b16 {%0,%1,%2,%3}, [%4];"
                 : "=r"(d0), "=r"(d1), "=r"(d2), "=r"(d3) : "r"(saddr));
}

__device__ __forceinline__ uint32_t smem_u32(const void* p) {
    uint32_t a;
    asm("{ .reg .u64 t; cvta.to.shared.u64 t, %1; cvt.u32.u64 %0, t; }"
        : "=r"(a) : "l"(p));
    return a;
}

__device__ __forceinline__ uint32_t h2pack(float x, float y) {
    __half2 h = __floats2half2_rn(x, y);
    return *(uint32_t*)&h;
}

// ---------------------------------------------------------------------------
// Kernel 0: transpose+fuse weights -> fp16 g_wth[n][k] (coalesced)
// ---------------------------------------------------------------------------
__global__ void wtrans(const float* __restrict__ Wq,
                       const float* __restrict__ Wk,
                       const float* __restrict__ Wv)
{
    __shared__ float s[64][65];
    const int wsel = blockIdx.x / 12;
    const int k0   = (blockIdx.x % 12) * 64;
    const float* W = (wsel == 0) ? Wq : (wsel == 1 ? Wk : Wv);
    const int tid = threadIdx.x;

#pragma unroll
    for (int r = 0; r < 16; r++) {
        int idx = r * 256 + tid;
        int k = idx >> 6, h = idx & 63;
        s[k][h] = W[(size_t)(k0 + k) * Hh + h];
    }
    __syncthreads();

#pragma unroll
    for (int r = 0; r < 8; r++) {
        int idx = r * 256 + tid;
        int h = idx >> 5, kw = idx & 31;
        g_wth[(size_t)(wsel * 64 + h) * (Cc / 2) + (k0 >> 1) + kw] =
            h2pack(s[2 * kw][h], s[2 * kw + 1][h]);
    }
}

// ---------------------------------------------------------------------------
// Kernel 1: QKV projection (unchanged from R15 — fp32 x, inline convert).
// ---------------------------------------------------------------------------
#define BKh 32
#define NCH (Cc / BKh)
#define W_A 0
#define W_B 5120
#define QKV_SMEM (12800 * 4)

__global__ __launch_bounds__(256) void qkv_h(const float* __restrict__ x)
{
    extern __shared__ uint32_t smw[];
    const uint32_t sb = smem_u32(smw);

    const int tid  = threadIdx.x;
    const int lane = tid & 31, wid = tid >> 5;
    const int m0   = blockIdx.x * 128;
    const int g    = lane >> 2, tig = lane & 3;
    const int wm   = wid & 3,  wn  = wid >> 2;

    int rowA[2], cwA[2], rowB[3], cwB[3];
#pragma unroll
    for (int r = 0; r < 2; r++) { int idx = r*256+tid; rowA[r]=idx>>2; cwA[r]=(idx&3)<<2; }
#pragma unroll
    for (int r = 0; r < 3; r++) { int idx = r*256+tid; rowB[r]=idx>>2; cwB[r]=(idx&3)<<2; }

    const int a_lrow = wm * 32 + (lane & 15);
    const int a_kh   = ((lane >> 4) & 1) << 2;
    const int b_lrow = wn * 96 + ((lane >> 4) & 1) * 8 + (lane & 7);
    const int b_kh   = ((lane >> 3) & 1) << 2;

    float acc[2][12][4];
#pragma unroll
    for (int i = 0; i < 2; i++)
#pragma unroll
        for (int j = 0; j < 12; j++)
#pragma unroll
            for (int r = 0; r < 4; r++) acc[i][j][r] = 0.f;

#pragma unroll
    for (int r = 0; r < 2; r++) {
        const float* xp = x + (size_t)(m0 + rowA[r]) * Cc + 2 * cwA[r];
        float4 f0 = *(const float4*)xp;
        float4 f1 = *(const float4*)(xp + 4);
        *(uint4*)&smw[W_A + rowA[r] * 20 + cwA[r]] =
            make_uint4(h2pack(f0.x, f0.y), h2pack(f0.z, f0.w),
                       h2pack(f1.x, f1.y), h2pack(f1.z, f1.w));
    }
#pragma unroll
    for (int r = 0; r < 3; r++)
        *(uint4*)&smw[W_B + rowB[r] * 20 + cwB[r]] =
            *(const uint4*)&g_wth[(size_t)rowB[r] * (Cc/2) + cwB[r]];
    __syncthreads();

    for (int t = 0; t < NCH; t++) {
        const int buf = t & 1;
        float4 stA0[2], stA1[2];
        uint4 stB[3];
        if (t + 1 < NCH) {
            const int k0f = (t + 1) * BKh;
            const int k0w = (t + 1) * (BKh / 2);
#pragma unroll
            for (int r = 0; r < 2; r++) {
                const float* xp = x + (size_t)(m0 + rowA[r]) * Cc + k0f + 2 * cwA[r];
                stA0[r] = *(const float4*)xp;
                stA1[r] = *(const float4*)(xp + 4);
            }
#pragma unroll
            for (int r = 0; r < 3; r++)
                stB[r] = *(const uint4*)&g_wth[(size_t)rowB[r] * (Cc/2) + k0w + cwB[r]];
        }

        const uint32_t Abase = sb + (W_A + buf * 2560) * 4;
        const uint32_t Bbase = sb + (W_B + buf * 3840) * 4;

#pragma unroll
        for (int kk2 = 0; kk2 < 16; kk2 += 8) {
            uint32_t a[2][4];
#pragma unroll
            for (int i = 0; i < 2; i++)
                ldsm_x4(a[i][0], a[i][1], a[i][2], a[i][3],
                        Abase + (uint32_t)(((a_lrow + i * 16) * 20 + kk2 + a_kh) * 4));
            uint32_t bf[12][2];
#pragma unroll
            for (int p = 0; p < 6; p++) {
                uint32_t d0, d1, d2, d3;
                ldsm_x4(d0, d1, d2, d3,
                        Bbase + (uint32_t)(((b_lrow + p * 16) * 20 + kk2 + b_kh) * 4));
                bf[2*p][0] = d0; bf[2*p][1] = d1;
                bf[2*p+1][0] = d2; bf[2*p+1][1] = d3;
            }
#pragma unroll
            for (int j = 0; j < 12; j++) {
                mma_fp16(acc[0][j], a[0], bf[j][0], bf[j][1]);
                mma_fp16(acc[1][j], a[1], bf[j][0], bf[j][1]);
            }
        }

        if (t + 1 < NCH) {
            uint32_t* Ad = smw + W_A + (buf ^ 1) * 2560;
            uint32_t* Bd = smw + W_B + (buf ^ 1) * 3840;
#pragma unroll
            for (int r = 0; r < 2; r++)
                *(uint4*)&Ad[rowA[r] * 20 + cwA[r]] =
                    make_uint4(h2pack(stA0[r].x, stA0[r].y), h2pack(stA0[r].z, stA0[r].w),
                               h2pack(stA1[r].x, stA1[r].y), h2pack(stA1[r].z, stA1[r].w));
#pragma unroll
            for (int r = 0; r < 3; r++)
                *(uint4*)&Bd[rowB[r] * 20 + cwB[r]] = stB[r];
        }
        __syncthreads();
    }

#pragma unroll
    for (int i = 0; i < 2; i++) {
        int r0 = m0 + wm * 32 + i * 16 + g;
#pragma unroll
        for (int j = 0; j < 12; j++) {
            int c = wn * 96 + j * 8 + tig * 2;
            uint32_t* op = (c < 64) ? g_qh : (c < 128 ? g_kh : g_vh);
            int oc = (c & 63) >> 1;
            op[(size_t)r0 * 32 + oc]       = h2pack(acc[i][j][0], acc[i][j][1]);
            op[(size_t)(r0 + 8) * 32 + oc] = h2pack(acc[i][j][2], acc[i][j][3]);
        }
    }
}

// ---------------------------------------------------------------------------
// Kernel 2: causal flash attention (unchanged from R15).
// ---------------------------------------------------------------------------
#define OQ  0
#define OKV 4608
#define ATTN_SMEM (13824 * 4)

__global__ __launch_bounds__(256, 2) void attn_mma(
    const float* __restrict__ amask)
{
    extern __shared__ uint32_t smw[];
    uint32_t* Qs = smw + OQ;
    const uint32_t sb = smem_u32(smw);

    const int b   = blockIdx.y;
    const int x   = blockIdx.x;
    int iq, part, ns;
    if (x < 16)      { iq = 15 - (x >> 2);        part = x & 3;        ns = 4; }
    else if (x < 28) { iq = 11 - (x - 16) / 3;    part = (x - 16) % 3; ns = 3; }
    else if (x < 36) { iq = 7  - ((x - 28) >> 1); part = (x - 28) & 1; ns = 2; }
    else             { iq = 3  - (x - 36);        part = 0;            ns = 1; }

    const int q0  = iq * 128;
    const int ntiles = 2 * iq + 2;
    const int base = ntiles / ns, rem = ntiles % ns;
    const int tstart = part * base + min(part, rem);
    const int tend   = tstart + base + (part < rem ? 1 : 0);

    const int tid = threadIdx.x;
    const int lane = tid & 31, w = tid >> 5;
    const int g = lane >> 2, t = lane & 3;

    const int a_lrow = w * 16 + (lane & 15);
    const int a_kh   = ((lane >> 4) & 1) << 2;
    const int b_lrow = ((lane >> 4) & 1) * 8 + (lane & 7);
    const int b_kh   = ((lane >> 3) & 1) << 2;

    // stage Q
    const uint32_t* qp = g_qh + ((size_t)b * Tt + q0) * 32;
#pragma unroll
    for (int r = 0; r < 4; r++) {
        int idx = r * 256 + tid;
        int row = idx >> 3, cw = (idx & 7) << 2;
        *(uint4*)&Qs[row * 36 + cw] = *(const uint4*)&qp[row * 32 + cw];
    }

    float m0 = -INFINITY, m1 = -INFINITY, l0 = 0.f, l1 = 0.f;
    float o[8][4];
#pragma unroll
    for (int f = 0; f < 8; f++)
#pragma unroll
        for (int r = 0; r < 4; r++) o[f][r] = 0.f;

    const float am0 = amask[(size_t)b * Tt + q0 + w * 16 + g];
    const float am1 = amask[(size_t)b * Tt + q0 + w * 16 + g + 8];
    const int qg0 = q0 + w * 16 + g;
    const int qg1 = qg0 + 8;

    int srow[2], scw[2];
#pragma unroll
    for (int r = 0; r < 2; r++) { int idx = r*256+tid; srow[r]=idx>>3; scw[r]=(idx&7)<<2; }

    // prologue: stage tile tstart into buffer 0
    {
        const uint32_t* kp = g_kh + ((size_t)b * Tt + tstart * 64) * 32;
        const uint32_t* vp = g_vh + ((size_t)b * Tt + tstart * 64) * 32;
        uint32_t* Kd = smw + OKV;
        uint32_t* Vd = smw + OKV + 2304;
#pragma unroll
        for (int r = 0; r < 2; r++) {
            *(uint4*)&Kd[srow[r] * 36 + scw[r]] = *(const uint4*)&kp[srow[r] * 32 + scw[r]];
            *(uint4*)&Vd[srow[r] * 36 + scw[r]] = *(const uint4*)&vp[srow[r] * 32 + scw[r]];
        }
    }
    __syncthreads();

    for (int tt = tstart; tt < tend; tt++) {
        const int cur = (tt - tstart) & 1;
        const int j0 = tt * 64;
        const bool more = (tt + 1 < tend);
        const bool interior = (j0 + 63 <= q0);

        uint4 stK[2], stV[2];
        if (more) {
            const uint32_t* kp = g_kh + ((size_t)b * Tt + (tt + 1) * 64) * 32;
            const uint32_t* vp = g_vh + ((size_t)b * Tt + (tt + 1) * 64) * 32;
#pragma unroll
            for (int r = 0; r < 2; r++) {
                stK[r] = *(const uint4*)&kp[srow[r] * 32 + scw[r]];
                stV[r] = *(const uint4*)&vp[srow[r] * 32 + scw[r]];
            }
        }

        const uint32_t sbq = sb;
        const uint32_t sbk = sb + (uint32_t)((OKV + cur * 4608) * 4);
        const uint32_t sbv = sb + (uint32_t)((OKV + cur * 4608 + 2304) * 4);

        // S = Q K^T
        float c[8][4];
#pragma unroll
        for (int f = 0; f < 8; f++)
#pragma unroll
            for (int r = 0; r < 4; r++) c[f][r] = 0.f;
#pragma unroll
        for (int ks = 0; ks < 4; ks++) {
            uint32_t a[4];
            ldsm_x4(a[0], a[1], a[2], a[3],
                    sbq + (uint32_t)((a_lrow * 36 + ks * 8 + a_kh) * 4));
            uint32_t bf[8][2];
#pragma unroll
            for (int p = 0; p < 4; p++) {
                uint32_t d0, d1, d2, d3;
                ldsm_x4(d0, d1, d2, d3,
                        sbk + (uint32_t)(((b_lrow + p * 16) * 36 + ks * 8 + b_kh) * 4));
                bf[2*p][0] = d0; bf[2*p][1] = d1;
                bf[2*p+1][0] = d2; bf[2*p+1][1] = d3;
            }
#pragma unroll
            for (int f = 0; f < 8; f++)
                mma_fp16(c[f], a, bf[f][0], bf[f][1]);
        }

        // masks
        float mx0 = -INFINITY, mx1 = -INFINITY;
        if (interior) {
#pragma unroll
            for (int f = 0; f < 8; f++) {
                float v0 = c[f][0] * 0.125f * am0;
                float v1 = c[f][1] * 0.125f * am0;
                float v2 = c[f][2] * 0.125f * am1;
                float v3 = c[f][3] * 0.125f * am1;
                if (v0 == 0.f) v0 = -INFINITY;
                if (v1 == 0.f) v1 = -INFINITY;
                if (v2 == 0.f) v2 = -INFINITY;
                if (v3 == 0.f) v3 = -INFINITY;
                c[f][0] = v0; c[f][1] = v1; c[f][2] = v2; c[f][3] = v3;
                mx0 = fmaxf(mx0, fmaxf(v0, v1));
                mx1 = fmaxf(mx1, fmaxf(v2, v3));
            }
        } else {
#pragma unroll
            for (int f = 0; f < 8; f++) {
                int col = j0 + f * 8 + t * 2;
                float v0 = c[f][0] * 0.125f * am0;
                float v1 = c[f][1] * 0.125f * am0;
                float v2 = c[f][2] * 0.125f * am1;
                float v3 = c[f][3] * 0.125f * am1;
                if (v0 == 0.f || col     > qg0) v0 = -INFINITY;
                if (v1 == 0.f || col + 1 > qg0) v1 = -INFINITY;
                if (v2 == 0.f || col     > qg1) v2 = -INFINITY;
                if (v3 == 0.f || col + 1 > qg1) v3 = -INFINITY;
                c[f][0] = v0; c[f][1] = v1; c[f][2] = v2; c[f][3] = v3;
                mx0 = fmaxf(mx0, fmaxf(v0, v1));
                mx1 = fmaxf(mx1, fmaxf(v2, v3));
            }
        }
        mx0 = fmaxf(mx0, __shfl_xor_sync(0xffffffffu, mx0, 1));
        mx0 = fmaxf(mx0, __shfl_xor_sync(0xffffffffu, mx0, 2));
        mx1 = fmaxf(mx1, __shfl_xor_sync(0xffffffffu, mx1, 1));
        mx1 = fmaxf(mx1, __shfl_xor_sync(0xffffffffu, mx1, 2));

        float mn0 = fmaxf(m0, mx0), mn1 = fmaxf(m1, mx1);
        float alpha0, alpha1, ls0 = 0.f, ls1 = 0.f;
        uint32_t p01[8], p23[8];
        if (mn0 == -INFINITY) {
            alpha0 = 1.f;
#pragma unroll
            for (int f = 0; f < 8; f++) { c[f][0] = 0.f; c[f][1] = 0.f; }
        } else {
            alpha0 = __expf(m0 - mn0);
#pragma unroll
            for (int f = 0; f < 8; f++) {
                c[f][0] = __expf(c[f][0] - mn0);
                c[f][1] = __expf(c[f][1] - mn0);
                ls0 += c[f][0] + c[f][1];
            }
        }
        if (mn1 == -INFINITY) {
            alpha1 = 1.f;
#pragma unroll
            for (int f = 0; f < 8; f++) { c[f][2] = 0.f; c[f][3] = 0.f; }
        } else {
            alpha1 = __expf(m1 - mn1);
#pragma unroll
            for (int f = 0; f < 8; f++) {
                c[f][2] = __expf(c[f][2] - mn1);
                c[f][3] = __expf(c[f][3] - mn1);
                ls1 += c[f][2] + c[f][3];
            }
        }
        m0 = mn0; m1 = mn1;
        ls0 += __shfl_xor_sync(0xffffffffu, ls0, 1);
        ls0 += __shfl_xor_sync(0xffffffffu, ls0, 2);
        ls1 += __shfl_xor_sync(0xffffffffu, ls1, 1);
        ls1 += __shfl_xor_sync(0xffffffffu, ls1, 2);
        l0 = l0 * alpha0 + ls0;
        l1 = l1 * alpha1 + ls1;

#pragma unroll
        for (int f = 0; f < 8; f++) {
            p01[f] = h2pack(c[f][0], c[f][1]);
            p23[f] = h2pack(c[f][2], c[f][3]);
            o[f][0] *= alpha0; o[f][1] *= alpha0;
            o[f][2] *= alpha1; o[f][3] *= alpha1;
        }

        // O += P V
        const int vrow = (lane & 15);
        const int vcb  = ((lane >> 4) & 1) << 2;
#pragma unroll
        for (int ss = 0; ss < 4; ss++) {
            uint32_t a[4];
            a[0] = p01[2 * ss];     a[1] = p23[2 * ss];
            a[2] = p01[2 * ss + 1]; a[3] = p23[2 * ss + 1];
#pragma unroll
            for (int p = 0; p < 4; p++) {
                uint32_t d0, d1, d2, d3;
                ldsm_x4_t(d0, d1, d2, d3,
                          sbv + (uint32_t)((((ss * 16 + vrow) * 36) + p * 8 + vcb) * 4));
                mma_fp16(o[2 * p],     a, d0, d1);
                mma_fp16(o[2 * p + 1], a, d2, d3);
            }
        }

        if (more) {
            uint32_t* Kd = smw + OKV + (cur ^ 1) * 4608;
            uint32_t* Vd = Kd + 2304;
#pragma unroll
            for (int r = 0; r < 2; r++) {
                *(uint4*)&Kd[srow[r] * 36 + scw[r]] = stK[r];
                *(uint4*)&Vd[srow[r] * 36 + scw[r]] = stV[r];
            }
        }
        __syncthreads();
    }

    // epilogue: write unnormalized partials into slot `part`
    float* po0 = g_po + ((size_t)part * M_TOT + (size_t)b * Tt + qg0) * 64;
    float* po1 = g_po + ((size_t)part * M_TOT + (size_t)b * Tt + qg1) * 64;
#pragma unroll
    for (int f = 0; f < 8; f++) {
        int col = f * 8 + t * 2;
        *(float2*)(po0 + col) = make_float2(o[f][0], o[f][1]);
        *(float2*)(po1 + col) = make_float2(o[f][2], o[f][3]);
    }
    if (t == 0) {
        size_t r0 = (size_t)part * M_TOT + (size_t)b * Tt + qg0;
        size_t r1 = (size_t)part * M_TOT + (size_t)b * Tt + qg1;
        g_pm[r0] = m0; g_pl[r0] = l0;
        g_pm[r1] = m1; g_pl[r1] = l1;
    }
}

// ---------------------------------------------------------------------------
// Kernel 3: combine — compile-time-unrolled per ns (independent LDGs, MLP>=4)
// ---------------------------------------------------------------------------
template <int NS>
__device__ __forceinline__ void comb_n(float* __restrict__ out, int row, int c4)
{
    float mv[NS], lv[NS];
    float4 a[NS];
#pragma unroll
    for (int s = 0; s < NS; s++) {
        mv[s] = g_pm[(size_t)s * M_TOT + row];
        lv[s] = g_pl[(size_t)s * M_TOT + row];
        a[s]  = *(const float4*)&g_po[((size_t)s * M_TOT + row) * 64 + c4];
    }
    float M = mv[0];
#pragma unroll
    for (int s = 1; s < NS; s++) M = fmaxf(M, mv[s]);
    float l = 0.f, wv[NS];
#pragma unroll
    for (int s = 0; s < NS; s++) {
        wv[s] = (mv[s] == -INFINITY) ? 0.f : __expf(mv[s] - M);
        l += lv[s] * wv[s];
    }
    float inv = (l > 0.f) ? (1.f / l) : 0.f;
    float4 acc = make_float4(0.f, 0.f, 0.f, 0.f);
#pragma unroll
    for (int s = 0; s < NS; s++) {
        acc.x += a[s].x * wv[s]; acc.y += a[s].y * wv[s];
        acc.z += a[s].z * wv[s]; acc.w += a[s].w * wv[s];
    }
    acc.x *= inv; acc.y *= inv; acc.z *= inv; acc.w *= inv;
    *(float4*)&out[(size_t)row * 64 + c4] = acc;
}

__global__ void combine(float* __restrict__ out)
{
    int idx = blockIdx.x * 256 + threadIdx.x;
    int row = idx >> 4;
    int c4  = (idx & 15) << 2;
    int iq  = (row & (Tt - 1)) >> 7;

    if (iq >= 12)      comb_n<4>(out, row, c4);
    else if (iq >= 8)  comb_n<3>(out, row, c4);
    else if (iq >= 4)  comb_n<2>(out, row, c4);
    else {
        // ns == 1 fast path: just normalize
        float l = g_pl[row];
        float inv = (l > 0.f) ? (1.f / l) : 0.f;
        float4 a = *(const float4*)&g_po[(size_t)row * 64 + c4];
        a.x *= inv; a.y *= inv; a.z *= inv; a.w *= inv;
        *(float4*)&out[(size_t)row * 64 + c4] = a;
    }
}

// ---------------------------------------------------------------------------
extern "C" void kernel_launch(void* const* d_in, const int* in_sizes, int n_in,
                              void* d_out, int out_size)
{
    const float* x  = (const float*)d_in[0];
    const float* am = (const float*)d_in[1];
    const float* Wq = (const float*)d_in[2];
    const float* Wk = (const float*)d_in[3];
    const float* Wv = (const float*)d_in[4];
    float*       out = (float*)d_out;

    wtrans<<<36, 256>>>(Wq, Wk, Wv);

    cudaFuncSetAttribute(qkv_h,
                         cudaFuncAttributeMaxDynamicSharedMemorySize, QKV_SMEM);
    qkv_h<<<M_TOT / 128, 256, QKV_SMEM>>>(x);

    cudaFuncSetAttribute(attn_mma,
                         cudaFuncAttributeMaxDynamicSharedMemorySize, ATTN_SMEM);
    dim3 g2(40, Bb);
    attn_mma<<<g2, 256, ATTN_SMEM>>>(am);

    combine<<<(M_TOT * 16) / 256, 256>>>(out);
}

// round 17
// speedup vs baseline: 1.3095x; 1.0342x over previous
#include <cuda_runtime.h>
#include <cuda_fp16.h>
#include <math.h>
#include <stdint.h>

#define Bb 8
#define Tt 2048
#define Cc 768
#define Hh 64
#define M_TOT (Bb*Tt)

// 0.125 * log2(e)  — S-scale folded with base-2 exponent domain
#define SSCALE 0.1803368801111204f

// fp16 scratch (half2 packed in uint32)
__device__ uint32_t g_wth[192*Cc/2];     // fused transposed weights fp16 [n][k]
__device__ uint32_t g_qh[M_TOT*32];      // q fp16 [row][h]
__device__ uint32_t g_kh[M_TOT*32];
__device__ uint32_t g_vh[M_TOT*32];
// split-KV partials (up to 4 splits); m is in log2 domain
__device__ float g_po[4 * M_TOT * 64];
__device__ float g_pm[4 * M_TOT];
__device__ float g_pl[4 * M_TOT];

// ---------------------------------------------------------------------------
// helpers
// ---------------------------------------------------------------------------
__device__ __forceinline__ void mma_fp16(float* d, const uint32_t* a,
                                         uint32_t b0, uint32_t b1) {
    asm volatile(
        "mma.sync.aligned.m16n8k16.row.col.f32.f16.f16.f32 "
        "{%0,%1,%2,%3}, {%4,%5,%6,%7}, {%8,%9}, {%0,%1,%2,%3};"
        : "+f"(d[0]), "+f"(d[1]), "+f"(d[2]), "+f"(d[3])
        : "r"(a[0]), "r"(a[1]), "r"(a[2]), "r"(a[3]), "r"(b0), "r"(b1));
}

__device__ __forceinline__ void ldsm_x4(uint32_t& d0, uint32_t& d1,
                                        uint32_t& d2, uint32_t& d3,
                                        uint32_t saddr) {
    asm volatile("ldmatrix.sync.aligned.m8n8.x4.shared.b16 {%0,%1,%2,%3}, [%4];"
                 : "=r"(d0), "=r"(d1), "=r"(d2), "=r"(d3) : "r"(saddr));
}

__device__ __forceinline__ void ldsm_x4_t(uint32_t& d0, uint32_t& d1,
                                          uint32_t& d2, uint32_t& d3,
                                          uint32_t saddr) {
    asm volatile("ldmatrix.sync.aligned.m8n8.x4.trans.shared.b16 {%0,%1,%2,%3}, [%4];"
                 : "=r"(d0), "=r"(d1), "=r"(d2), "=r"(d3) : "r"(saddr));
}

__device__ __forceinline__ uint32_t smem_u32(const void* p) {
    uint32_t a;
    asm("{ .reg .u64 t; cvta.to.shared.u64 t, %1; cvt.u32.u64 %0, t; }"
        : "=r"(a) : "l"(p));
    return a;
}

__device__ __forceinline__ uint32_t h2pack(float x, float y) {
    __half2 h = __floats2half2_rn(x, y);
    return *(uint32_t*)&h;
}

// raw MUFU.EX2 (2^x); ex2(-inf) = 0
__device__ __forceinline__ float ex2f(float x) {
    float r;
    asm("ex2.approx.f32 %0, %1;" : "=f"(r) : "f"(x));
    return r;
}

// ---------------------------------------------------------------------------
// Kernel 0: transpose+fuse weights -> fp16 g_wth[n][k] (coalesced)
// ---------------------------------------------------------------------------
__global__ void wtrans(const float* __restrict__ Wq,
                       const float* __restrict__ Wk,
                       const float* __restrict__ Wv)
{
    __shared__ float s[64][65];
    const int wsel = blockIdx.x / 12;
    const int k0   = (blockIdx.x % 12) * 64;
    const float* W = (wsel == 0) ? Wq : (wsel == 1 ? Wk : Wv);
    const int tid = threadIdx.x;

#pragma unroll
    for (int r = 0; r < 16; r++) {
        int idx = r * 256 + tid;
        int k = idx >> 6, h = idx & 63;
        s[k][h] = W[(size_t)(k0 + k) * Hh + h];
    }
    __syncthreads();

#pragma unroll
    for (int r = 0; r < 8; r++) {
        int idx = r * 256 + tid;
        int h = idx >> 5, kw = idx & 31;
        g_wth[(size_t)(wsel * 64 + h) * (Cc / 2) + (k0 >> 1) + kw] =
            h2pack(s[2 * kw][h], s[2 * kw + 1][h]);
    }
}

// ---------------------------------------------------------------------------
// Kernel 1: QKV projection (unchanged — fp32 x, inline convert).
// ---------------------------------------------------------------------------
#define BKh 32
#define NCH (Cc / BKh)
#define W_A 0
#define W_B 5120
#define QKV_SMEM (12800 * 4)

__global__ __launch_bounds__(256) void qkv_h(const float* __restrict__ x)
{
    extern __shared__ uint32_t smw[];
    const uint32_t sb = smem_u32(smw);

    const int tid  = threadIdx.x;
    const int lane = tid & 31, wid = tid >> 5;
    const int m0   = blockIdx.x * 128;
    const int g    = lane >> 2, tig = lane & 3;
    const int wm   = wid & 3,  wn  = wid >> 2;

    int rowA[2], cwA[2], rowB[3], cwB[3];
#pragma unroll
    for (int r = 0; r < 2; r++) { int idx = r*256+tid; rowA[r]=idx>>2; cwA[r]=(idx&3)<<2; }
#pragma unroll
    for (int r = 0; r < 3; r++) { int idx = r*256+tid; rowB[r]=idx>>2; cwB[r]=(idx&3)<<2; }

    const int a_lrow = wm * 32 + (lane & 15);
    const int a_kh   = ((lane >> 4) & 1) << 2;
    const int b_lrow = wn * 96 + ((lane >> 4) & 1) * 8 + (lane & 7);
    const int b_kh   = ((lane >> 3) & 1) << 2;

    float acc[2][12][4];
#pragma unroll
    for (int i = 0; i < 2; i++)
#pragma unroll
        for (int j = 0; j < 12; j++)
#pragma unroll
            for (int r = 0; r < 4; r++) acc[i][j][r] = 0.f;

#pragma unroll
    for (int r = 0; r < 2; r++) {
        const float* xp = x + (size_t)(m0 + rowA[r]) * Cc + 2 * cwA[r];
        float4 f0 = *(const float4*)xp;
        float4 f1 = *(const float4*)(xp + 4);
        *(uint4*)&smw[W_A + rowA[r] * 20 + cwA[r]] =
            make_uint4(h2pack(f0.x, f0.y), h2pack(f0.z, f0.w),
                       h2pack(f1.x, f1.y), h2pack(f1.z, f1.w));
    }
#pragma unroll
    for (int r = 0; r < 3; r++)
        *(uint4*)&smw[W_B + rowB[r] * 20 + cwB[r]] =
            *(const uint4*)&g_wth[(size_t)rowB[r] * (Cc/2) + cwB[r]];
    __syncthreads();

    for (int t = 0; t < NCH; t++) {
        const int buf = t & 1;
        float4 stA0[2], stA1[2];
        uint4 stB[3];
        if (t + 1 < NCH) {
            const int k0f = (t + 1) * BKh;
            const int k0w = (t + 1) * (BKh / 2);
#pragma unroll
            for (int r = 0; r < 2; r++) {
                const float* xp = x + (size_t)(m0 + rowA[r]) * Cc + k0f + 2 * cwA[r];
                stA0[r] = *(const float4*)xp;
                stA1[r] = *(const float4*)(xp + 4);
            }
#pragma unroll
            for (int r = 0; r < 3; r++)
                stB[r] = *(const uint4*)&g_wth[(size_t)rowB[r] * (Cc/2) + k0w + cwB[r]];
        }

        const uint32_t Abase = sb + (W_A + buf * 2560) * 4;
        const uint32_t Bbase = sb + (W_B + buf * 3840) * 4;

#pragma unroll
        for (int kk2 = 0; kk2 < 16; kk2 += 8) {
            uint32_t a[2][4];
#pragma unroll
            for (int i = 0; i < 2; i++)
                ldsm_x4(a[i][0], a[i][1], a[i][2], a[i][3],
                        Abase + (uint32_t)(((a_lrow + i * 16) * 20 + kk2 + a_kh) * 4));
            uint32_t bf[12][2];
#pragma unroll
            for (int p = 0; p < 6; p++) {
                uint32_t d0, d1, d2, d3;
                ldsm_x4(d0, d1, d2, d3,
                        Bbase + (uint32_t)(((b_lrow + p * 16) * 20 + kk2 + b_kh) * 4));
                bf[2*p][0] = d0; bf[2*p][1] = d1;
                bf[2*p+1][0] = d2; bf[2*p+1][1] = d3;
            }
#pragma unroll
            for (int j = 0; j < 12; j++) {
                mma_fp16(acc[0][j], a[0], bf[j][0], bf[j][1]);
                mma_fp16(acc[1][j], a[1], bf[j][0], bf[j][1]);
            }
        }

        if (t + 1 < NCH) {
            uint32_t* Ad = smw + W_A + (buf ^ 1) * 2560;
            uint32_t* Bd = smw + W_B + (buf ^ 1) * 3840;
#pragma unroll
            for (int r = 0; r < 2; r++)
                *(uint4*)&Ad[rowA[r] * 20 + cwA[r]] =
                    make_uint4(h2pack(stA0[r].x, stA0[r].y), h2pack(stA0[r].z, stA0[r].w),
                               h2pack(stA1[r].x, stA1[r].y), h2pack(stA1[r].z, stA1[r].w));
#pragma unroll
            for (int r = 0; r < 3; r++)
                *(uint4*)&Bd[rowB[r] * 20 + cwB[r]] = stB[r];
        }
        __syncthreads();
    }

#pragma unroll
    for (int i = 0; i < 2; i++) {
        int r0 = m0 + wm * 32 + i * 16 + g;
#pragma unroll
        for (int j = 0; j < 12; j++) {
            int c = wn * 96 + j * 8 + tig * 2;
            uint32_t* op = (c < 64) ? g_qh : (c < 128 ? g_kh : g_vh);
            int oc = (c & 63) >> 1;
            op[(size_t)r0 * 32 + oc]       = h2pack(acc[i][j][0], acc[i][j][1]);
            op[(size_t)(r0 + 8) * 32 + oc] = h2pack(acc[i][j][2], acc[i][j][3]);
        }
    }
}

// ---------------------------------------------------------------------------
// Kernel 2: causal flash attention, adaptive split-KV, ldmatrix S-path.
// log2-domain softmax: scale = 0.125*log2e*am folded once; exp = MUFU.EX2.
// ---------------------------------------------------------------------------
#define OQ  0
#define OKV 4608
#define ATTN_SMEM (13824 * 4)

__global__ __launch_bounds__(256, 2) void attn_mma(
    const float* __restrict__ amask)
{
    extern __shared__ uint32_t smw[];
    uint32_t* Qs = smw + OQ;
    const uint32_t sb = smem_u32(smw);

    const int b   = blockIdx.y;
    const int x   = blockIdx.x;
    int iq, part, ns;
    if (x < 16)      { iq = 15 - (x >> 2);        part = x & 3;        ns = 4; }
    else if (x < 28) { iq = 11 - (x - 16) / 3;    part = (x - 16) % 3; ns = 3; }
    else if (x < 36) { iq = 7  - ((x - 28) >> 1); part = (x - 28) & 1; ns = 2; }
    else             { iq = 3  - (x - 36);        part = 0;            ns = 1; }

    const int q0  = iq * 128;
    const int ntiles = 2 * iq + 2;
    const int base = ntiles / ns, rem = ntiles % ns;
    const int tstart = part * base + min(part, rem);
    const int tend   = tstart + base + (part < rem ? 1 : 0);

    const int tid = threadIdx.x;
    const int lane = tid & 31, w = tid >> 5;
    const int g = lane >> 2, t = lane & 3;

    const int a_lrow = w * 16 + (lane & 15);
    const int a_kh   = ((lane >> 4) & 1) << 2;
    const int b_lrow = ((lane >> 4) & 1) * 8 + (lane & 7);
    const int b_kh   = ((lane >> 3) & 1) << 2;

    // stage Q
    const uint32_t* qp = g_qh + ((size_t)b * Tt + q0) * 32;
#pragma unroll
    for (int r = 0; r < 4; r++) {
        int idx = r * 256 + tid;
        int row = idx >> 3, cw = (idx & 7) << 2;
        *(uint4*)&Qs[row * 36 + cw] = *(const uint4*)&qp[row * 32 + cw];
    }

    float m0 = -INFINITY, m1 = -INFINITY, l0 = 0.f, l1 = 0.f;
    float o[8][4];
#pragma unroll
    for (int f = 0; f < 8; f++)
#pragma unroll
        for (int r = 0; r < 4; r++) o[f][r] = 0.f;

    // folded scale: 0.125 * log2(e) * am  (log2-domain logits)
    const float ssc0 = amask[(size_t)b * Tt + q0 + w * 16 + g]     * SSCALE;
    const float ssc1 = amask[(size_t)b * Tt + q0 + w * 16 + g + 8] * SSCALE;
    const int qg0 = q0 + w * 16 + g;
    const int qg1 = qg0 + 8;

    int srow[2], scw[2];
#pragma unroll
    for (int r = 0; r < 2; r++) { int idx = r*256+tid; srow[r]=idx>>3; scw[r]=(idx&7)<<2; }

    // prologue: stage tile tstart into buffer 0
    {
        const uint32_t* kp = g_kh + ((size_t)b * Tt + tstart * 64) * 32;
        const uint32_t* vp = g_vh + ((size_t)b * Tt + tstart * 64) * 32;
        uint32_t* Kd = smw + OKV;
        uint32_t* Vd = smw + OKV + 2304;
#pragma unroll
        for (int r = 0; r < 2; r++) {
            *(uint4*)&Kd[srow[r] * 36 + scw[r]] = *(const uint4*)&kp[srow[r] * 32 + scw[r]];
            *(uint4*)&Vd[srow[r] * 36 + scw[r]] = *(const uint4*)&vp[srow[r] * 32 + scw[r]];
        }
    }
    __syncthreads();

    for (int tt = tstart; tt < tend; tt++) {
        const int cur = (tt - tstart) & 1;
        const int j0 = tt * 64;
        const bool more = (tt + 1 < tend);
        const bool interior = (j0 + 63 <= q0);

        uint4 stK[2], stV[2];
        if (more) {
            const uint32_t* kp = g_kh + ((size_t)b * Tt + (tt + 1) * 64) * 32;
            const uint32_t* vp = g_vh + ((size_t)b * Tt + (tt + 1) * 64) * 32;
#pragma unroll
            for (int r = 0; r < 2; r++) {
                stK[r] = *(const uint4*)&kp[srow[r] * 32 + scw[r]];
                stV[r] = *(const uint4*)&vp[srow[r] * 32 + scw[r]];
            }
        }

        const uint32_t sbq = sb;
        const uint32_t sbk = sb + (uint32_t)((OKV + cur * 4608) * 4);
        const uint32_t sbv = sb + (uint32_t)((OKV + cur * 4608 + 2304) * 4);

        // S = Q K^T (fragments via ldmatrix)
        float c[8][4];
#pragma unroll
        for (int f = 0; f < 8; f++)
#pragma unroll
            for (int r = 0; r < 4; r++) c[f][r] = 0.f;
#pragma unroll
        for (int ks = 0; ks < 4; ks++) {
            uint32_t a[4];
            ldsm_x4(a[0], a[1], a[2], a[3],
                    sbq + (uint32_t)((a_lrow * 36 + ks * 8 + a_kh) * 4));
            uint32_t bf[8][2];
#pragma unroll
            for (int p = 0; p < 4; p++) {
                uint32_t d0, d1, d2, d3;
                ldsm_x4(d0, d1, d2, d3,
                        sbk + (uint32_t)(((b_lrow + p * 16) * 36 + ks * 8 + b_kh) * 4));
                bf[2*p][0] = d0; bf[2*p][1] = d1;
                bf[2*p+1][0] = d2; bf[2*p+1][1] = d3;
            }
#pragma unroll
            for (int f = 0; f < 8; f++)
                mma_fp16(c[f], a, bf[f][0], bf[f][1]);
        }

        // masks (single FMUL per element; log2-domain values)
        float mx0 = -INFINITY, mx1 = -INFINITY;
        if (interior) {
#pragma unroll
            for (int f = 0; f < 8; f++) {
                float v0 = c[f][0] * ssc0;
                float v1 = c[f][1] * ssc0;
                float v2 = c[f][2] * ssc1;
                float v3 = c[f][3] * ssc1;
                if (v0 == 0.f) v0 = -INFINITY;
                if (v1 == 0.f) v1 = -INFINITY;
                if (v2 == 0.f) v2 = -INFINITY;
                if (v3 == 0.f) v3 = -INFINITY;
                c[f][0] = v0; c[f][1] = v1; c[f][2] = v2; c[f][3] = v3;
                mx0 = fmaxf(mx0, fmaxf(v0, v1));
                mx1 = fmaxf(mx1, fmaxf(v2, v3));
            }
        } else {
#pragma unroll
            for (int f = 0; f < 8; f++) {
                int col = j0 + f * 8 + t * 2;
                float v0 = c[f][0] * ssc0;
                float v1 = c[f][1] * ssc0;
                float v2 = c[f][2] * ssc1;
                float v3 = c[f][3] * ssc1;
                if (v0 == 0.f || col     > qg0) v0 = -INFINITY;
                if (v1 == 0.f || col + 1 > qg0) v1 = -INFINITY;
                if (v2 == 0.f || col     > qg1) v2 = -INFINITY;
                if (v3 == 0.f || col + 1 > qg1) v3 = -INFINITY;
                c[f][0] = v0; c[f][1] = v1; c[f][2] = v2; c[f][3] = v3;
                mx0 = fmaxf(mx0, fmaxf(v0, v1));
                mx1 = fmaxf(mx1, fmaxf(v2, v3));
            }
        }
        mx0 = fmaxf(mx0, __shfl_xor_sync(0xffffffffu, mx0, 1));
        mx0 = fmaxf(mx0, __shfl_xor_sync(0xffffffffu, mx0, 2));
        mx1 = fmaxf(mx1, __shfl_xor_sync(0xffffffffu, mx1, 1));
        mx1 = fmaxf(mx1, __shfl_xor_sync(0xffffffffu, mx1, 2));

        float mn0 = fmaxf(m0, mx0), mn1 = fmaxf(m1, mx1);
        float alpha0, alpha1, ls0 = 0.f, ls1 = 0.f;
        uint32_t p01[8], p23[8];
        if (mn0 == -INFINITY) {
            alpha0 = 1.f;
#pragma unroll
            for (int f = 0; f < 8; f++) { c[f][0] = 0.f; c[f][1] = 0.f; }
        } else {
            alpha0 = ex2f(m0 - mn0);
#pragma unroll
            for (int f = 0; f < 8; f++) {
                c[f][0] = ex2f(c[f][0] - mn0);
                c[f][1] = ex2f(c[f][1] - mn0);
                ls0 += c[f][0] + c[f][1];
            }
        }
        if (mn1 == -INFINITY) {
            alpha1 = 1.f;
#pragma unroll
            for (int f = 0; f < 8; f++) { c[f][2] = 0.f; c[f][3] = 0.f; }
        } else {
            alpha1 = ex2f(m1 - mn1);
#pragma unroll
            for (int f = 0; f < 8; f++) {
                c[f][2] = ex2f(c[f][2] - mn1);
                c[f][3] = ex2f(c[f][3] - mn1);
                ls1 += c[f][2] + c[f][3];
            }
        }
        m0 = mn0; m1 = mn1;
        ls0 += __shfl_xor_sync(0xffffffffu, ls0, 1);
        ls0 += __shfl_xor_sync(0xffffffffu, ls0, 2);
        ls1 += __shfl_xor_sync(0xffffffffu, ls1, 1);
        ls1 += __shfl_xor_sync(0xffffffffu, ls1, 2);
        l0 = l0 * alpha0 + ls0;
        l1 = l1 * alpha1 + ls1;

#pragma unroll
        for (int f = 0; f < 8; f++) {
            p01[f] = h2pack(c[f][0], c[f][1]);
            p23[f] = h2pack(c[f][2], c[f][3]);
            o[f][0] *= alpha0; o[f][1] *= alpha0;
            o[f][2] *= alpha1; o[f][3] *= alpha1;
        }

        // O += P V
        const int vrow = (lane & 15);
        const int vcb  = ((lane >> 4) & 1) << 2;
#pragma unroll
        for (int ss = 0; ss < 4; ss++) {
            uint32_t a[4];
            a[0] = p01[2 * ss];     a[1] = p23[2 * ss];
            a[2] = p01[2 * ss + 1]; a[3] = p23[2 * ss + 1];
#pragma unroll
            for (int p = 0; p < 4; p++) {
                uint32_t d0, d1, d2, d3;
                ldsm_x4_t(d0, d1, d2, d3,
                          sbv + (uint32_t)((((ss * 16 + vrow) * 36) + p * 8 + vcb) * 4));
                mma_fp16(o[2 * p],     a, d0, d1);
                mma_fp16(o[2 * p + 1], a, d2, d3);
            }
        }

        if (more) {
            uint32_t* Kd = smw + OKV + (cur ^ 1) * 4608;
            uint32_t* Vd = Kd + 2304;
#pragma unroll
            for (int r = 0; r < 2; r++) {
                *(uint4*)&Kd[srow[r] * 36 + scw[r]] = stK[r];
                *(uint4*)&Vd[srow[r] * 36 + scw[r]] = stV[r];
            }
        }
        __syncthreads();
    }

    // epilogue: write unnormalized partials into slot `part` (m in log2 domain)
    float* po0 = g_po + ((size_t)part * M_TOT + (size_t)b * Tt + qg0) * 64;
    float* po1 = g_po + ((size_t)part * M_TOT + (size_t)b * Tt + qg1) * 64;
#pragma unroll
    for (int f = 0; f < 8; f++) {
        int col = f * 8 + t * 2;
        *(float2*)(po0 + col) = make_float2(o[f][0], o[f][1]);
        *(float2*)(po1 + col) = make_float2(o[f][2], o[f][3]);
    }
    if (t == 0) {
        size_t r0 = (size_t)part * M_TOT + (size_t)b * Tt + qg0;
        size_t r1 = (size_t)part * M_TOT + (size_t)b * Tt + qg1;
        g_pm[r0] = m0; g_pl[r0] = l0;
        g_pm[r1] = m1; g_pl[r1] = l1;
    }
}

// ---------------------------------------------------------------------------
// Kernel 3: combine — compile-time-unrolled per ns; merge weights via ex2
// (m values are in log2 domain).
// ---------------------------------------------------------------------------
template <int NS>
__device__ __forceinline__ void comb_n(float* __restrict__ out, int row, int c4)
{
    float mv[NS], lv[NS];
    float4 a[NS];
#pragma unroll
    for (int s = 0; s < NS; s++) {
        mv[s] = g_pm[(size_t)s * M_TOT + row];
        lv[s] = g_pl[(size_t)s * M_TOT + row];
        a[s]  = *(const float4*)&g_po[((size_t)s * M_TOT + row) * 64 + c4];
    }
    float M = mv[0];
#pragma unroll
    for (int s = 1; s < NS; s++) M = fmaxf(M, mv[s]);
    float l = 0.f, wv[NS];
#pragma unroll
    for (int s = 0; s < NS; s++) {
        wv[s] = (mv[s] == -INFINITY) ? 0.f : ex2f(mv[s] - M);
        l += lv[s] * wv[s];
    }
    float inv = (l > 0.f) ? (1.f / l) : 0.f;
    float4 acc = make_float4(0.f, 0.f, 0.f, 0.f);
#pragma unroll
    for (int s = 0; s < NS; s++) {
        acc.x += a[s].x * wv[s]; acc.y += a[s].y * wv[s];
        acc.z += a[s].z * wv[s]; acc.w += a[s].w * wv[s];
    }
    acc.x *= inv; acc.y *= inv; acc.z *= inv; acc.w *= inv;
    *(float4*)&out[(size_t)row * 64 + c4] = acc;
}

__global__ void combine(float* __restrict__ out)
{
    int idx = blockIdx.x * 256 + threadIdx.x;
    int row = idx >> 4;
    int c4  = (idx & 15) << 2;
    int iq  = (row & (Tt - 1)) >> 7;

    if (iq >= 12)      comb_n<4>(out, row, c4);
    else if (iq >= 8)  comb_n<3>(out, row, c4);
    else if (iq >= 4)  comb_n<2>(out, row, c4);
    else {
        float l = g_pl[row];
        float inv = (l > 0.f) ? (1.f / l) : 0.f;
        float4 a = *(const float4*)&g_po[(size_t)row * 64 + c4];
        a.x *= inv; a.y *= inv; a.z *= inv; a.w *= inv;
        *(float4*)&out[(size_t)row * 64 + c4] = a;
    }
}

// ---------------------------------------------------------------------------
extern "C" void kernel_launch(void* const* d_in, const int* in_sizes, int n_in,
                              void* d_out, int out_size)
{
    const float* x  = (const float*)d_in[0];
    const float* am = (const float*)d_in[1];
    const float* Wq = (const float*)d_in[2];
    const float* Wk = (const float*)d_in[3];
    const float* Wv = (const float*)d_in[4];
    float*       out = (float*)d_out;

    wtrans<<<36, 256>>>(Wq, Wk, Wv);

    cudaFuncSetAttribute(qkv_h,
                         cudaFuncAttributeMaxDynamicSharedMemorySize, QKV_SMEM);
    qkv_h<<<M_TOT / 128, 256, QKV_SMEM>>>(x);

    cudaFuncSetAttribute(attn_mma,
                         cudaFuncAttributeMaxDynamicSharedMemorySize, ATTN_SMEM);
    dim3 g2(40, Bb);
    attn_mma<<<g2, 256, ATTN_SMEM>>>(am);

    combine<<<(M_TOT * 16) / 256, 256>>>(out);
}